// round 2
// baseline (speedup 1.0000x reference)
#include <cuda_runtime.h>
#include <cuda_fp16.h>
#include <math.h>

#define N_NODES 32768
#define N_EDGES 8192
#define ND 128
#define ED 128
#define HD 64
#define OD 128
#define NH 4
#define EPSV 1e-8f

// ---------------- scratch ----------------
__device__ __half g_te[(size_t)N_EDGES * 256];
__device__ float  g_agg[(size_t)N_NODES * 256];
__device__ float  g_bufA[(size_t)N_NODES * OD];
__device__ float  g_bufB[(size_t)N_NODES * OD];
__device__ float  g_cmin[NH * OD];
__device__ float  g_cmax[NH * OD];

// ---------------- helpers ----------------
__device__ __forceinline__ void atomicMinF(float* addr, float value) {
    if (value >= 0.f) atomicMin((int*)addr, __float_as_int(value));
    else              atomicMax((unsigned int*)addr, __float_as_uint(value));
}
__device__ __forceinline__ void atomicMaxF(float* addr, float value) {
    if (value >= 0.f) atomicMax((int*)addr, __float_as_int(value));
    else              atomicMin((unsigned int*)addr, __float_as_uint(value));
}
// packed fp32 FMA: 2 exact fp32 FMAs per instruction (FFMA2), ptxas never emits from C++
__device__ __forceinline__ void ffma2(float2& c, float2 a, float2 b) {
    asm("fma.rn.f32x2 %0, %1, %2, %0;"
        : "+l"(*reinterpret_cast<unsigned long long*>(&c))
        : "l"(*reinterpret_cast<const unsigned long long*>(&a)),
          "l"(*reinterpret_cast<const unsigned long long*>(&b)));
}

// ---------------- kernel 0 ----------------
__global__ void init_minmax_kernel(float* cmin, float* cmax) {
    int t = threadIdx.x;
    cmin[t] =  __int_as_float(0x7f800000);
    cmax[t] = -__int_as_float(0x7f800000);
}

// ---------------- kernel 1: te (all heads, fp16) ----------------
__global__ void te_kernel(const float* __restrict__ ef, const float* __restrict__ edgeW,
                          const float* __restrict__ edgeB, __half* __restrict__ te) {
    __shared__ float sef[32][ED + 1];
    int t = threadIdx.x;
    int e0 = blockIdx.x * 32;
#pragma unroll
    for (int i = 0; i < 16; i++) {
        int L = i * 256 + t;
        int r = L >> 7, q = L & 127;
        sef[r][q] = ef[(size_t)(e0 + r) * ED + q];
    }
    __syncthreads();
    int h = t >> 6, c = t & 63;
    const float* W = edgeW + (size_t)h * ED * HD + c;
    float acc[32];
#pragma unroll
    for (int r = 0; r < 32; r++) acc[r] = 0.f;
    for (int k = 0; k < ED; k++) {
        float w = __ldg(W + k * HD);
#pragma unroll
        for (int r = 0; r < 32; r++) acc[r] += sef[r][k] * w;
    }
    float b = edgeB[h * HD + c];
#pragma unroll
    for (int r = 0; r < 32; r++)
        te[(size_t)(e0 + r) * 256 + t] = __float2half(acc[r] + b);
}

// ---------------- kernel 2: scan. no smem atomics — per-warp segments ----------------
#define SEG_CAP 96
__global__ void scan_kernel(const float* __restrict__ inc, const __half* __restrict__ te,
                            float* __restrict__ agg) {
    __shared__ int s_idx[8][SEG_CAP];
    __shared__ int s_cnt[8];
    int t = threadIdx.x, w = t >> 5, l = t & 31;
    int n = blockIdx.x;

    const float4* row = (const float4*)(inc + (size_t)n * N_EDGES);
    int cnt = 0;  // warp-uniform running count
#pragma unroll
    for (int i = 0; i < 8; i++) {
        int j = i * 256 + t;
        float4 v = __ldcs(row + j);
        int m = (v.x != 0.f ? 1 : 0) | (v.y != 0.f ? 2 : 0) |
                (v.z != 0.f ? 4 : 0) | (v.w != 0.f ? 8 : 0);
        int c = __popc(m);
        // warp inclusive scan of c
        int pre = c;
#pragma unroll
        for (int d = 1; d < 32; d <<= 1) {
            int o = __shfl_up_sync(0xffffffffu, pre, d);
            if (l >= d) pre += o;
        }
        int total = __shfl_sync(0xffffffffu, pre, 31);
        int base = cnt + (pre - c);
        int e0 = j * 4;
        if (base + c <= SEG_CAP) {
            if (m & 1) s_idx[w][base++] = e0;
            if (m & 2) s_idx[w][base++] = e0 + 1;
            if (m & 4) s_idx[w][base++] = e0 + 2;
            if (m & 8) s_idx[w][base++] = e0 + 3;
        }
        cnt += total;
    }
    if (l == 0) s_cnt[w] = min(cnt, SEG_CAP);
    __syncthreads();

    int deg = 0;
#pragma unroll
    for (int w2 = 0; w2 < 8; w2++) deg += s_cnt[w2];
    float inv = 1.f / ((float)deg + EPSV);

    float a0 = 0.f, a1 = 0.f, a2 = 0.f, a3 = 0.f;
#pragma unroll
    for (int w2 = 0; w2 < 8; w2++) {
        int c2 = s_cnt[w2];
        const int* seg = &s_idx[w2][0];
        int m = 0;
        for (; m + 4 <= c2; m += 4) {
            a0 += __half2float(__ldg(&te[(size_t)seg[m + 0] * 256 + t]));
            a1 += __half2float(__ldg(&te[(size_t)seg[m + 1] * 256 + t]));
            a2 += __half2float(__ldg(&te[(size_t)seg[m + 2] * 256 + t]));
            a3 += __half2float(__ldg(&te[(size_t)seg[m + 3] * 256 + t]));
        }
        for (; m < c2; m++)
            a0 += __half2float(__ldg(&te[(size_t)seg[m] * 256 + t]));
    }
    agg[(size_t)n * 256 + t] = ((a0 + a1) + (a2 + a3)) * inv;
}

// ---------------- kernel 3: fused head (FFMA2, transposed tiles, norm-on-load) ----------------
// smem: sxT[128][68] fp32, stn[64][68] (c-major; tn then u), sag[64][68] (c-major), sat[64], sg[64]
__global__ __launch_bounds__(256) void head_kernel(
    const float* __restrict__ x, const float* __restrict__ agg,
    const float* __restrict__ nodeW, const float* __restrict__ nodeB,
    const float* __restrict__ attnW, const float* __restrict__ attnB,
    const float* __restrict__ outW,  const float* __restrict__ outB,
    int h, float* __restrict__ upd,
    float* __restrict__ cmin, float* __restrict__ cmax,
    const float* __restrict__ pmin, const float* __restrict__ pmax) {
    extern __shared__ float sm[];
    float* sxT = sm;                  // 128*68
    float* stn = sxT + 128 * 68;      // 64*68
    float* sag = stn + 64 * 68;       // 64*68
    float* sat = sag + 64 * 68;       // 64
    float* sg  = sat + 64;            // 64

    int t = threadIdx.x;
    int n0 = blockIdx.x * 64;
    bool dn = (pmin != nullptr);

    // per-thread norm params (loader column q = t&127 is fixed)
    float xm = 0.f, xs = 1.f;
    if (dn) {
        float mn = pmin[t & 127], mx = pmax[t & 127];
        xm = mn; xs = 1.f / (mx - mn + EPSV);
    }

    // ---- loads: x (transposed, normalized), agg (transposed), attnW ----
#pragma unroll
    for (int i = 0; i < 32; i++) {
        int L = i * 256 + t;
        int r = L >> 7, q = L & 127;
        float v = x[(size_t)(n0 + r) * ND + q];
        if (dn) v = fmaxf(0.f, (v - xm) * xs);
        sxT[q * 68 + r] = v;
    }
#pragma unroll
    for (int i = 0; i < 16; i++) {
        int L = i * 256 + t;
        int r = L >> 6, c = L & 63;
        sag[c * 68 + r] = agg[(size_t)(n0 + r) * 256 + h * 64 + c];
    }
    if (t < 64) sat[t] = attnW[h * 64 + t];
    __syncthreads();

    // ---- stage 2: tn = x @ nodeW + nodeB  (4 rows x 4 cols / thread, FFMA2) ----
    {
        int cg = t & 15, ng = t >> 4;
        int c0 = cg * 4, r0 = ng * 4;
        const float4* W4 = (const float4*)(nodeW + (size_t)h * ND * HD);
        float2 acc[4][2];
#pragma unroll
        for (int i = 0; i < 4; i++) { acc[i][0] = make_float2(0.f, 0.f); acc[i][1] = make_float2(0.f, 0.f); }
#pragma unroll 4
        for (int k = 0; k < ND; k++) {
            float4 xv = *(const float4*)&sxT[k * 68 + r0];
            float4 wv = __ldg(&W4[k * 16 + cg]);
            float2 w01 = make_float2(wv.x, wv.y), w23 = make_float2(wv.z, wv.w);
            float xr[4] = {xv.x, xv.y, xv.z, xv.w};
#pragma unroll
            for (int i = 0; i < 4; i++) {
                float2 xx = make_float2(xr[i], xr[i]);
                ffma2(acc[i][0], xx, w01);
                ffma2(acc[i][1], xx, w23);
            }
        }
        float4 nb = *(const float4*)&nodeB[h * HD + c0];
#pragma unroll
        for (int i = 0; i < 4; i++) {
            stn[(c0 + 0) * 68 + r0 + i] = acc[i][0].x + nb.x;
            stn[(c0 + 1) * 68 + r0 + i] = acc[i][0].y + nb.y;
            stn[(c0 + 2) * 68 + r0 + i] = acc[i][1].x + nb.z;
            stn[(c0 + 3) * 68 + r0 + i] = acc[i][1].y + nb.w;
        }
    }
    __syncthreads();

    // ---- scores + gate: 4 threads per row ----
    {
        int r = t >> 2, sub = t & 3;
        float s = 0.f;
#pragma unroll
        for (int cc = 0; cc < 16; cc++) {
            int c = sub * 16 + cc;
            s += (stn[c * 68 + r] + sag[c * 68 + r]) * sat[c];
        }
        s += __shfl_xor_sync(0xffffffffu, s, 1);
        s += __shfl_xor_sync(0xffffffffu, s, 2);
        if (sub == 0) {
            s += attnB[h];
            s = (s >= 0.f) ? s : 0.2f * s;
            sg[r] = 1.f / (1.f + expf(-s));
        }
    }
    __syncthreads();

    // ---- u = g*agg + tn (in place) ----
#pragma unroll
    for (int i = 0; i < 16; i++) {
        int L = i * 256 + t;
        int c = L >> 6, r = L & 63;
        stn[c * 68 + r] += sg[r] * sag[c * 68 + r];
    }
    __syncthreads();

    // ---- stage 3: upd = u @ outW + outB  (8 rows x 4 cols / thread, FFMA2) ----
    {
        int jg = t & 31, rg = t >> 5;
        int j0 = jg * 4, r0 = rg * 8;
        const float4* W4 = (const float4*)(outW + (size_t)h * HD * OD);
        float2 acc[8][2];
#pragma unroll
        for (int i = 0; i < 8; i++) { acc[i][0] = make_float2(0.f, 0.f); acc[i][1] = make_float2(0.f, 0.f); }
#pragma unroll 2
        for (int c = 0; c < HD; c++) {
            float4 u0 = *(const float4*)&stn[c * 68 + r0];
            float4 u1 = *(const float4*)&stn[c * 68 + r0 + 4];
            float4 wv = __ldg(&W4[c * 32 + jg]);
            float2 w01 = make_float2(wv.x, wv.y), w23 = make_float2(wv.z, wv.w);
            float ur[8] = {u0.x, u0.y, u0.z, u0.w, u1.x, u1.y, u1.z, u1.w};
#pragma unroll
            for (int i = 0; i < 8; i++) {
                float2 uu = make_float2(ur[i], ur[i]);
                ffma2(acc[i][0], uu, w01);
                ffma2(acc[i][1], uu, w23);
            }
        }
        float4 ob = *(const float4*)&outB[h * OD + j0];
        float4 vmin = make_float4(3.4e38f, 3.4e38f, 3.4e38f, 3.4e38f);
        float4 vmax = make_float4(-3.4e38f, -3.4e38f, -3.4e38f, -3.4e38f);
#pragma unroll
        for (int i = 0; i < 8; i++) {
            float4 o;
            o.x = acc[i][0].x + ob.x; o.y = acc[i][0].y + ob.y;
            o.z = acc[i][1].x + ob.z; o.w = acc[i][1].y + ob.w;
            *(float4*)&upd[(size_t)(n0 + r0 + i) * OD + j0] = o;
            vmin.x = fminf(vmin.x, o.x); vmax.x = fmaxf(vmax.x, o.x);
            vmin.y = fminf(vmin.y, o.y); vmax.y = fmaxf(vmax.y, o.y);
            vmin.z = fminf(vmin.z, o.z); vmax.z = fmaxf(vmax.z, o.z);
            vmin.w = fminf(vmin.w, o.w); vmax.w = fmaxf(vmax.w, o.w);
        }
        __syncthreads();                    // stn/sag reads done; reuse sag for reduction
        float* smin = sag;                  // [8][128]
        float* smax = sag + 1024;           // [8][128]
        smin[rg * 128 + j0 + 0] = vmin.x; smax[rg * 128 + j0 + 0] = vmax.x;
        smin[rg * 128 + j0 + 1] = vmin.y; smax[rg * 128 + j0 + 1] = vmax.y;
        smin[rg * 128 + j0 + 2] = vmin.z; smax[rg * 128 + j0 + 2] = vmax.z;
        smin[rg * 128 + j0 + 3] = vmin.w; smax[rg * 128 + j0 + 3] = vmax.w;
    }
    __syncthreads();
    if (t < 128) {
        float* smin = sag;
        float* smax = sag + 1024;
        float m = smin[t], M = smax[t];
#pragma unroll
        for (int rg = 1; rg < 8; rg++) {
            m = fminf(m, smin[rg * 128 + t]);
            M = fmaxf(M, smax[rg * 128 + t]);
        }
        atomicMinF(&cmin[t], m);
        atomicMaxF(&cmax[t], M);
    }
}

// ---------------- kernel 4: final norm ----------------
__global__ void norm_kernel(const float4* __restrict__ upd, const float* __restrict__ cmin,
                            const float* __restrict__ cmax, float4* __restrict__ dst) {
    __shared__ float sa[128], sb[128];
    int t = threadIdx.x;
    if (t < 128) {
        float mn = cmin[t], mx = cmax[t];
        sa[t] = 1.f / (mx - mn + EPSV);
        sb[t] = mn;
    }
    __syncthreads();
    int i = blockIdx.x * 256 + t;
    float4 v = upd[i];
    int c = (i & 31) * 4;
    float4 o;
    o.x = fmaxf(0.f, (v.x - sb[c + 0]) * sa[c + 0]);
    o.y = fmaxf(0.f, (v.y - sb[c + 1]) * sa[c + 1]);
    o.z = fmaxf(0.f, (v.z - sb[c + 2]) * sa[c + 2]);
    o.w = fmaxf(0.f, (v.w - sb[c + 3]) * sa[c + 3]);
    dst[i] = o;
}

// ---------------- launch ----------------
extern "C" void kernel_launch(void* const* d_in, const int* in_sizes, int n_in,
                              void* d_out, int out_size) {
    const float* nodeF = (const float*)d_in[0];
    const float* inc   = (const float*)d_in[1];
    const float* edgeF = (const float*)d_in[2];
    const float* nodeW = (const float*)d_in[3];
    const float* nodeB = (const float*)d_in[4];
    const float* edgeW = (const float*)d_in[5];
    const float* edgeB = (const float*)d_in[6];
    const float* attnW = (const float*)d_in[7];
    const float* attnB = (const float*)d_in[8];
    const float* outW  = (const float*)d_in[9];
    const float* outB  = (const float*)d_in[10];

    __half* te;  float *agg, *bufA, *bufB, *cmin, *cmax;
    cudaGetSymbolAddress((void**)&te,   g_te);
    cudaGetSymbolAddress((void**)&agg,  g_agg);
    cudaGetSymbolAddress((void**)&bufA, g_bufA);
    cudaGetSymbolAddress((void**)&bufB, g_bufB);
    cudaGetSymbolAddress((void**)&cmin, g_cmin);
    cudaGetSymbolAddress((void**)&cmax, g_cmax);

    size_t hk_smem = (size_t)(128 * 68 + 64 * 68 + 64 * 68 + 64 + 64) * sizeof(float);
    cudaFuncSetAttribute(head_kernel, cudaFuncAttributeMaxDynamicSharedMemorySize, (int)hk_smem);

    init_minmax_kernel<<<1, NH * OD>>>(cmin, cmax);
    te_kernel<<<N_EDGES / 32, 256>>>(edgeF, edgeW, edgeB, te);
    scan_kernel<<<N_NODES, 256>>>(inc, te, agg);

    float* bufs[2] = { bufA, bufB };
    const float* xin = nodeF;
    for (int h = 0; h < NH; h++) {
        float* dst = bufs[h & 1];
        const float* pmin = (h == 0) ? nullptr : cmin + (h - 1) * 128;
        const float* pmax = (h == 0) ? nullptr : cmax + (h - 1) * 128;
        head_kernel<<<N_NODES / 64, 256, hk_smem>>>(xin, agg, nodeW, nodeB, attnW, attnB,
                                                    outW, outB, h, dst,
                                                    cmin + h * 128, cmax + h * 128,
                                                    pmin, pmax);
        xin = dst;
    }
    norm_kernel<<<(N_NODES * OD / 4) / 256, 256>>>((const float4*)bufs[(NH - 1) & 1],
                                                   cmin + (NH - 1) * 128, cmax + (NH - 1) * 128,
                                                   (float4*)d_out);
}

// round 3
// speedup vs baseline: 1.5087x; 1.5087x over previous
#include <cuda_runtime.h>
#include <cuda_fp16.h>
#include <math.h>

#define N_NODES 32768
#define N_EDGES 8192
#define ND 128
#define ED 128
#define HD 64
#define OD 128
#define NH 4
#define EPSV 1e-8f

// ---------------- scratch ----------------
__device__ __half g_te[(size_t)N_EDGES * 256];
__device__ float  g_agg[(size_t)N_NODES * 256];
__device__ float  g_bufA[(size_t)N_NODES * OD];
__device__ float  g_bufB[(size_t)N_NODES * OD];
__device__ float  g_cmin[NH * OD];
__device__ float  g_cmax[NH * OD];

// ---------------- helpers ----------------
__device__ __forceinline__ void atomicMinF(float* addr, float value) {
    if (value >= 0.f) atomicMin((int*)addr, __float_as_int(value));
    else              atomicMax((unsigned int*)addr, __float_as_uint(value));
}
__device__ __forceinline__ void atomicMaxF(float* addr, float value) {
    if (value >= 0.f) atomicMax((int*)addr, __float_as_int(value));
    else              atomicMin((unsigned int*)addr, __float_as_uint(value));
}

// ---------------- kernel 0 ----------------
__global__ void init_minmax_kernel(float* cmin, float* cmax) {
    int t = threadIdx.x;
    cmin[t] =  __int_as_float(0x7f800000);
    cmax[t] = -__int_as_float(0x7f800000);
}

// ---------------- kernel 1: te (all heads, fp16 out) ----------------
__global__ void te_kernel(const float* __restrict__ ef, const float* __restrict__ edgeW,
                          const float* __restrict__ edgeB, __half* __restrict__ te) {
    __shared__ float sef[32][ED + 1];
    int t = threadIdx.x;
    int e0 = blockIdx.x * 32;
#pragma unroll
    for (int i = 0; i < 16; i++) {
        int L = i * 256 + t;
        int r = L >> 7, q = L & 127;
        sef[r][q] = ef[(size_t)(e0 + r) * ED + q];
    }
    __syncthreads();
    int h = t >> 6, c = t & 63;
    const float* W = edgeW + (size_t)h * ED * HD + c;
    float acc[32];
#pragma unroll
    for (int r = 0; r < 32; r++) acc[r] = 0.f;
    for (int k = 0; k < ED; k++) {
        float w = __ldg(W + k * HD);
#pragma unroll
        for (int r = 0; r < 32; r++) acc[r] += sef[r][k] * w;
    }
    float b = edgeB[h * HD + c];
#pragma unroll
    for (int r = 0; r < 32; r++)
        te[(size_t)(e0 + r) * 256 + t] = __float2half(acc[r] + b);
}

// ---------------- kernel 2: scan — mask-register compaction, zero atomics ----------------
// Phase A: each thread loads its 8 float4 (batched -> full MLP), packs nonzero flags
//          into ONE 32-bit mask register. No inter-load dependencies.
// Phase B: popc/reduce/prefix -> contiguous compaction into s_idx.
// Phase C: gather-accumulate te rows (identical to R1's proven gather).
__global__ void scan_kernel(const float* __restrict__ inc, const __half* __restrict__ te,
                            float* __restrict__ agg) {
    __shared__ int s_idx[512];
    __shared__ int s_wcnt[8];
    int t = threadIdx.x, w = t >> 5, l = t & 31;
    int n = blockIdx.x;

    const float4* row = (const float4*)(inc + (size_t)n * N_EDGES);
    unsigned mask = 0u;
#pragma unroll
    for (int i = 0; i < 8; i++) {
        float4 v = __ldcs(row + i * 256 + t);
        unsigned m = (v.x != 0.f ? 1u : 0u) | (v.y != 0.f ? 2u : 0u) |
                     (v.z != 0.f ? 4u : 0u) | (v.w != 0.f ? 8u : 0u);
        mask |= m << (i * 4);
    }
    int myc = __popc(mask);
    // warp exclusive prefix + total (single 5-step scan, after ALL loads issued)
    int pre = myc;
#pragma unroll
    for (int d = 1; d < 32; d <<= 1) {
        int o = __shfl_up_sync(0xffffffffu, pre, d);
        if (l >= d) pre += o;
    }
    int wtot = __shfl_sync(0xffffffffu, pre, 31);
    int myoff = pre - myc;
    if (l == 0) s_wcnt[w] = wtot;
    __syncthreads();

    int base = 0, cnt = 0;
#pragma unroll
    for (int w2 = 0; w2 < 8; w2++) {
        int c2 = s_wcnt[w2];
        if (w2 < w) base += c2;
        cnt += c2;
    }
    int pos = base + myoff;
    // expand set bits: bit b -> i = b>>2, sub = b&3 -> edge id 4*(i*256+t)+sub
    unsigned mm = mask;
    while (mm) {
        int b = __ffs(mm) - 1;
        mm &= mm - 1;
        s_idx[pos++] = ((b >> 2) * 256 + t) * 4 + (b & 3);
    }
    __syncthreads();

    float inv = 1.f / ((float)cnt + EPSV);   // incidence entries are exactly 1.0

    float a0 = 0.f, a1 = 0.f, a2 = 0.f, a3 = 0.f;
    int m = 0;
    for (; m + 4 <= cnt; m += 4) {
        a0 += __half2float(__ldg(&te[(size_t)s_idx[m + 0] * 256 + t]));
        a1 += __half2float(__ldg(&te[(size_t)s_idx[m + 1] * 256 + t]));
        a2 += __half2float(__ldg(&te[(size_t)s_idx[m + 2] * 256 + t]));
        a3 += __half2float(__ldg(&te[(size_t)s_idx[m + 3] * 256 + t]));
    }
    for (; m < cnt; m++)
        a0 += __half2float(__ldg(&te[(size_t)s_idx[m] * 256 + t]));

    agg[(size_t)n * 256 + t] = ((a0 + a1) + (a2 + a3)) * inv;
}

// ---------------- kernel 3: fused head (R1 structure + norm-on-load) ----------------
__global__ void head_kernel(const float* __restrict__ x, const float* __restrict__ agg,
                            const float* __restrict__ nodeW, const float* __restrict__ nodeB,
                            const float* __restrict__ attnW, const float* __restrict__ attnB,
                            const float* __restrict__ outW,  const float* __restrict__ outB,
                            int h, float* __restrict__ upd,
                            float* __restrict__ cmin, float* __restrict__ cmax,
                            const float* __restrict__ pmin, const float* __restrict__ pmax) {
    extern __shared__ float sm[];
    float* sx    = sm;                    // [64][129] x tile
    float* sw    = sx + 64 * 129;         // 8192: nodeW (stage2) then outW (stage3)
    float* stn   = sw + 8192;             // [64][65]: tn, then u (in place)
    float* sagg  = stn + 64 * 65;         // [64][65]
    float* sattn = sagg + 64 * 65;        // 64
    float* sg    = sattn + 64;            // 64
    float* sred  = sx;                    // reuse for min/max reduction (2048)

    int t = threadIdx.x;
    int n0 = blockIdx.x * 64;
    bool dn = (pmin != nullptr);

    float xm = 0.f, xs = 1.f;             // norm params for this thread's fixed column q=t&127
    if (dn) {
        float mn = pmin[t & 127], mx = pmax[t & 127];
        xm = mn; xs = 1.f / (mx - mn + EPSV);
    }

    // ---- stage 1: loads ----
#pragma unroll
    for (int i = 0; i < 32; i++) {        // x tile 64x128, normalize+relu previous head on the fly
        int L = i * 256 + t;
        int r = L >> 7, q = L & 127;
        float v = x[(size_t)(n0 + r) * ND + q];
        if (dn) v = fmaxf(0.f, (v - xm) * xs);
        sx[r * 129 + q] = v;
    }
    const float* nw = nodeW + (size_t)h * ND * HD;
#pragma unroll
    for (int i = 0; i < 32; i++) sw[i * 256 + t] = nw[i * 256 + t];
#pragma unroll
    for (int i = 0; i < 16; i++) {        // agg tile 64x64 (head slice)
        int L = i * 256 + t;
        int r = L >> 6, c = L & 63;
        sagg[r * 65 + c] = agg[(size_t)(n0 + r) * 256 + h * 64 + c];
    }
    if (t < 64) sattn[t] = attnW[h * 64 + t];
    __syncthreads();

    // ---- stage 2: tn = x @ nodeW + nodeB ----
    {
        int cg = t >> 4, ng = t & 15;
        int c0 = cg * 4, r0 = ng * 4;
        float acc[4][4];
#pragma unroll
        for (int i = 0; i < 4; i++)
#pragma unroll
            for (int j = 0; j < 4; j++) acc[i][j] = 0.f;

        for (int k = 0; k < ND; k++) {
            float4 wv = *(const float4*)&sw[k * 64 + c0];
#pragma unroll
            for (int i = 0; i < 4; i++) {
                float xv = sx[(r0 + i) * 129 + k];
                acc[i][0] += xv * wv.x;
                acc[i][1] += xv * wv.y;
                acc[i][2] += xv * wv.z;
                acc[i][3] += xv * wv.w;
            }
        }
        float nb0 = nodeB[h * HD + c0 + 0];
        float nb1 = nodeB[h * HD + c0 + 1];
        float nb2 = nodeB[h * HD + c0 + 2];
        float nb3 = nodeB[h * HD + c0 + 3];
#pragma unroll
        for (int i = 0; i < 4; i++) {
            stn[(r0 + i) * 65 + c0 + 0] = acc[i][0] + nb0;
            stn[(r0 + i) * 65 + c0 + 1] = acc[i][1] + nb1;
            stn[(r0 + i) * 65 + c0 + 2] = acc[i][2] + nb2;
            stn[(r0 + i) * 65 + c0 + 3] = acc[i][3] + nb3;
        }
    }
    __syncthreads();

    // ---- scores + gate (64 threads), overlapped with outW load (all threads) ----
    if (t < 64) {
        int r = t;
        float s = attnB[h];
        for (int c = 0; c < 64; c++)
            s += (stn[r * 65 + c] + sagg[r * 65 + c]) * sattn[c];
        s = (s >= 0.f) ? s : 0.2f * s;
        sg[r] = 1.f / (1.f + expf(-s));
    }
    const float* ow = outW + (size_t)h * HD * OD;
#pragma unroll
    for (int i = 0; i < 32; i++) sw[i * 256 + t] = ow[i * 256 + t];
    __syncthreads();

    // ---- u = g*agg + tn (in place) ----
#pragma unroll
    for (int i = 0; i < 16; i++) {
        int L = i * 256 + t;
        int r = L >> 6, c = L & 63;
        stn[r * 65 + c] = sg[r] * sagg[r * 65 + c] + stn[r * 65 + c];
    }
    __syncthreads();

    // ---- stage 3: upd = u @ outW + outB, per-column min/max ----
    {
        int jg = t & 31, rg = t >> 5;
        int j0 = jg * 4, rr0 = rg * 8;
        float4 acc3[8];
#pragma unroll
        for (int i = 0; i < 8; i++) acc3[i] = make_float4(0.f, 0.f, 0.f, 0.f);

        for (int c = 0; c < HD; c++) {
            float4 wv = *(const float4*)&sw[c * 128 + j0];
#pragma unroll
            for (int i = 0; i < 8; i++) {
                float uv = stn[(rr0 + i) * 65 + c];
                acc3[i].x += uv * wv.x;
                acc3[i].y += uv * wv.y;
                acc3[i].z += uv * wv.z;
                acc3[i].w += uv * wv.w;
            }
        }
        float4 ob = *(const float4*)&outB[h * OD + j0];
        float lmin0 =  3.4e38f, lmin1 =  3.4e38f, lmin2 =  3.4e38f, lmin3 =  3.4e38f;
        float lmax0 = -3.4e38f, lmax1 = -3.4e38f, lmax2 = -3.4e38f, lmax3 = -3.4e38f;
#pragma unroll
        for (int i = 0; i < 8; i++) {
            float4 o;
            o.x = acc3[i].x + ob.x; o.y = acc3[i].y + ob.y;
            o.z = acc3[i].z + ob.z; o.w = acc3[i].w + ob.w;
            *(float4*)&upd[(size_t)(n0 + rr0 + i) * OD + j0] = o;
            lmin0 = fminf(lmin0, o.x); lmax0 = fmaxf(lmax0, o.x);
            lmin1 = fminf(lmin1, o.y); lmax1 = fmaxf(lmax1, o.y);
            lmin2 = fminf(lmin2, o.z); lmax2 = fmaxf(lmax2, o.z);
            lmin3 = fminf(lmin3, o.w); lmax3 = fmaxf(lmax3, o.w);
        }
        __syncthreads();               // sx done; reuse as sred
        float* smin = sred;            // [8][128]
        float* smax = sred + 1024;
        smin[rg * 128 + j0 + 0] = lmin0; smax[rg * 128 + j0 + 0] = lmax0;
        smin[rg * 128 + j0 + 1] = lmin1; smax[rg * 128 + j0 + 1] = lmax1;
        smin[rg * 128 + j0 + 2] = lmin2; smax[rg * 128 + j0 + 2] = lmax2;
        smin[rg * 128 + j0 + 3] = lmin3; smax[rg * 128 + j0 + 3] = lmax3;
    }
    __syncthreads();
    if (t < 128) {
        float* smin = sred;
        float* smax = sred + 1024;
        float m = smin[t], M = smax[t];
#pragma unroll
        for (int rg = 1; rg < 8; rg++) {
            m = fminf(m, smin[rg * 128 + t]);
            M = fmaxf(M, smax[rg * 128 + t]);
        }
        atomicMinF(&cmin[t], m);
        atomicMaxF(&cmax[t], M);
    }
}

// ---------------- kernel 4: final norm ----------------
__global__ void norm_kernel(const float4* __restrict__ upd, const float* __restrict__ cmin,
                            const float* __restrict__ cmax, float4* __restrict__ dst) {
    __shared__ float sa[128], sb[128];
    int t = threadIdx.x;
    if (t < 128) {
        float mn = cmin[t], mx = cmax[t];
        sa[t] = 1.f / (mx - mn + EPSV);
        sb[t] = mn;
    }
    __syncthreads();
    int i = blockIdx.x * 256 + t;
    float4 v = upd[i];
    int c = (i & 31) * 4;
    float4 o;
    o.x = fmaxf(0.f, (v.x - sb[c + 0]) * sa[c + 0]);
    o.y = fmaxf(0.f, (v.y - sb[c + 1]) * sa[c + 1]);
    o.z = fmaxf(0.f, (v.z - sb[c + 2]) * sa[c + 2]);
    o.w = fmaxf(0.f, (v.w - sb[c + 3]) * sa[c + 3]);
    dst[i] = o;
}

// ---------------- launch ----------------
extern "C" void kernel_launch(void* const* d_in, const int* in_sizes, int n_in,
                              void* d_out, int out_size) {
    const float* nodeF = (const float*)d_in[0];
    const float* inc   = (const float*)d_in[1];
    const float* edgeF = (const float*)d_in[2];
    const float* nodeW = (const float*)d_in[3];
    const float* nodeB = (const float*)d_in[4];
    const float* edgeW = (const float*)d_in[5];
    const float* edgeB = (const float*)d_in[6];
    const float* attnW = (const float*)d_in[7];
    const float* attnB = (const float*)d_in[8];
    const float* outW  = (const float*)d_in[9];
    const float* outB  = (const float*)d_in[10];

    __half* te;  float *agg, *bufA, *bufB, *cmin, *cmax;
    cudaGetSymbolAddress((void**)&te,   g_te);
    cudaGetSymbolAddress((void**)&agg,  g_agg);
    cudaGetSymbolAddress((void**)&bufA, g_bufA);
    cudaGetSymbolAddress((void**)&bufB, g_bufB);
    cudaGetSymbolAddress((void**)&cmin, g_cmin);
    cudaGetSymbolAddress((void**)&cmax, g_cmax);

    size_t hk_smem = (size_t)(64 * 129 + 8192 + 64 * 65 + 64 * 65 + 64 + 64) * sizeof(float);
    cudaFuncSetAttribute(head_kernel, cudaFuncAttributeMaxDynamicSharedMemorySize, (int)hk_smem);

    init_minmax_kernel<<<1, NH * OD>>>(cmin, cmax);
    te_kernel<<<N_EDGES / 32, 256>>>(edgeF, edgeW, edgeB, te);
    scan_kernel<<<N_NODES, 256>>>(inc, te, agg);

    float* bufs[2] = { bufA, bufB };
    const float* xin = nodeF;
    for (int h = 0; h < NH; h++) {
        float* dst = bufs[h & 1];
        const float* pmin = (h == 0) ? nullptr : cmin + (h - 1) * 128;
        const float* pmax = (h == 0) ? nullptr : cmax + (h - 1) * 128;
        head_kernel<<<N_NODES / 64, 256, hk_smem>>>(xin, agg, nodeW, nodeB, attnW, attnB,
                                                    outW, outB, h, dst,
                                                    cmin + h * 128, cmax + h * 128,
                                                    pmin, pmax);
        xin = dst;
    }
    norm_kernel<<<(N_NODES * OD / 4) / 256, 256>>>((const float4*)bufs[(NH - 1) & 1],
                                                   cmin + (NH - 1) * 128, cmax + (NH - 1) * 128,
                                                   (float4*)d_out);
}

// round 4
// speedup vs baseline: 2.1587x; 1.4308x over previous
#include <cuda_runtime.h>
#include <cuda_fp16.h>
#include <math.h>

#define N_NODES 32768
#define N_EDGES 8192
#define ND 128
#define ED 128
#define HD 64
#define OD 128
#define NH 4
#define EPSV 1e-8f

// ---------------- scratch ----------------
__device__ __half g_te[(size_t)N_EDGES * 256];
__device__ float  g_agg[(size_t)N_NODES * 256];
__device__ float  g_bufA[(size_t)N_NODES * OD];
__device__ float  g_bufB[(size_t)N_NODES * OD];
__device__ float  g_cmin[NH * OD];
__device__ float  g_cmax[NH * OD];

// ---------------- helpers ----------------
__device__ __forceinline__ void atomicMinF(float* addr, float value) {
    if (value >= 0.f) atomicMin((int*)addr, __float_as_int(value));
    else              atomicMax((unsigned int*)addr, __float_as_uint(value));
}
__device__ __forceinline__ void atomicMaxF(float* addr, float value) {
    if (value >= 0.f) atomicMax((int*)addr, __float_as_int(value));
    else              atomicMin((unsigned int*)addr, __float_as_uint(value));
}
__device__ __forceinline__ unsigned smem_u32(const void* p) {
    return (unsigned)__cvta_generic_to_shared(p);
}
__device__ __forceinline__ void ldm_x4(unsigned addr, unsigned& r0, unsigned& r1,
                                       unsigned& r2, unsigned& r3) {
    asm volatile("ldmatrix.sync.aligned.m8n8.x4.shared.b16 {%0,%1,%2,%3}, [%4];"
                 : "=r"(r0), "=r"(r1), "=r"(r2), "=r"(r3) : "r"(addr));
}
__device__ __forceinline__ void ldm_x4t(unsigned addr, unsigned& r0, unsigned& r1,
                                        unsigned& r2, unsigned& r3) {
    asm volatile("ldmatrix.sync.aligned.m8n8.x4.trans.shared.b16 {%0,%1,%2,%3}, [%4];"
                 : "=r"(r0), "=r"(r1), "=r"(r2), "=r"(r3) : "r"(addr));
}
__device__ __forceinline__ void mma16816(float& c0, float& c1, float& c2, float& c3,
                                         unsigned a0, unsigned a1, unsigned a2, unsigned a3,
                                         unsigned b0, unsigned b1) {
    asm volatile("mma.sync.aligned.m16n8k16.row.col.f32.f16.f16.f32 "
                 "{%0,%1,%2,%3},{%4,%5,%6,%7},{%8,%9},{%0,%1,%2,%3};"
                 : "+f"(c0), "+f"(c1), "+f"(c2), "+f"(c3)
                 : "r"(a0), "r"(a1), "r"(a2), "r"(a3), "r"(b0), "r"(b1));
}

// ---------------- kernel 0 ----------------
__global__ void init_minmax_kernel(float* cmin, float* cmax) {
    int t = threadIdx.x;
    cmin[t] =  __int_as_float(0x7f800000);
    cmax[t] = -__int_as_float(0x7f800000);
}

// ---------------- kernel 1: te (all heads, fp16 out) ----------------
__global__ void te_kernel(const float* __restrict__ ef, const float* __restrict__ edgeW,
                          const float* __restrict__ edgeB, __half* __restrict__ te) {
    __shared__ float sef[32][ED + 1];
    int t = threadIdx.x;
    int e0 = blockIdx.x * 32;
#pragma unroll
    for (int i = 0; i < 16; i++) {
        int L = i * 256 + t;
        int r = L >> 7, q = L & 127;
        sef[r][q] = ef[(size_t)(e0 + r) * ED + q];
    }
    __syncthreads();
    int h = t >> 6, c = t & 63;
    const float* W = edgeW + (size_t)h * ED * HD + c;
    float acc[32];
#pragma unroll
    for (int r = 0; r < 32; r++) acc[r] = 0.f;
    for (int k = 0; k < ED; k++) {
        float w = __ldg(W + k * HD);
#pragma unroll
        for (int r = 0; r < 32; r++) acc[r] += sef[r][k] * w;
    }
    float b = edgeB[h * HD + c];
#pragma unroll
    for (int r = 0; r < 32; r++)
        te[(size_t)(e0 + r) * 256 + t] = __float2half(acc[r] + b);
}

// ---------------- kernel 2: scan (mask compaction + half2 gather) ----------------
__global__ void scan_kernel(const float* __restrict__ inc, const __half* __restrict__ te,
                            float* __restrict__ agg) {
    __shared__ int s_idx[512];
    __shared__ int s_wcnt[8];
    __shared__ float sxch[256];
    int t = threadIdx.x, w = t >> 5, l = t & 31;
    int n = blockIdx.x;

    const float4* row = (const float4*)(inc + (size_t)n * N_EDGES);
    unsigned mask = 0u;
#pragma unroll
    for (int i = 0; i < 8; i++) {
        float4 v = __ldcs(row + i * 256 + t);
        unsigned m = (v.x != 0.f ? 1u : 0u) | (v.y != 0.f ? 2u : 0u) |
                     (v.z != 0.f ? 4u : 0u) | (v.w != 0.f ? 8u : 0u);
        mask |= m << (i * 4);
    }
    int myc = __popc(mask);
    int pre = myc;
#pragma unroll
    for (int d = 1; d < 32; d <<= 1) {
        int o = __shfl_up_sync(0xffffffffu, pre, d);
        if (l >= d) pre += o;
    }
    int wtot = __shfl_sync(0xffffffffu, pre, 31);
    int myoff = pre - myc;
    if (l == 0) s_wcnt[w] = wtot;
    __syncthreads();

    int base = 0, cnt = 0;
#pragma unroll
    for (int w2 = 0; w2 < 8; w2++) {
        int c2 = s_wcnt[w2];
        if (w2 < w) base += c2;
        cnt += c2;
    }
    int pos = base + myoff;
    unsigned mm = mask;
    while (mm) {
        int b = __ffs(mm) - 1;
        mm &= mm - 1;
        s_idx[pos++] = ((b >> 2) * 256 + t) * 4 + (b & 3);
    }
    __syncthreads();

    float inv = 1.f / ((float)cnt + EPSV);

    // half2 gather: thread = (parity p = t>>7, half2 col c2 = t&127)
    int p = t >> 7, c2 = t & 127;
    const __half2* te2 = (const __half2*)te;
    float2 a0 = make_float2(0.f, 0.f), a1 = make_float2(0.f, 0.f);
    float2 a2 = make_float2(0.f, 0.f), a3 = make_float2(0.f, 0.f);
    int m = p;
    for (; m + 6 < cnt; m += 8) {
        float2 v0 = __half22float2(__ldg(&te2[(size_t)s_idx[m + 0] * 128 + c2]));
        float2 v1 = __half22float2(__ldg(&te2[(size_t)s_idx[m + 2] * 128 + c2]));
        float2 v2 = __half22float2(__ldg(&te2[(size_t)s_idx[m + 4] * 128 + c2]));
        float2 v3 = __half22float2(__ldg(&te2[(size_t)s_idx[m + 6] * 128 + c2]));
        a0.x += v0.x; a0.y += v0.y; a1.x += v1.x; a1.y += v1.y;
        a2.x += v2.x; a2.y += v2.y; a3.x += v3.x; a3.y += v3.y;
    }
    for (; m < cnt; m += 2) {
        float2 v = __half22float2(__ldg(&te2[(size_t)s_idx[m] * 128 + c2]));
        a0.x += v.x; a0.y += v.y;
    }
    float2 acc = make_float2((a0.x + a1.x) + (a2.x + a3.x),
                             (a0.y + a1.y) + (a2.y + a3.y));
    __syncthreads();
    if (p == 1) { sxch[c2 * 2] = acc.x; sxch[c2 * 2 + 1] = acc.y; }
    __syncthreads();
    if (p == 0) {
        float2 o;
        o.x = (acc.x + sxch[c2 * 2]) * inv;
        o.y = (acc.y + sxch[c2 * 2 + 1]) * inv;
        *(float2*)&agg[(size_t)n * 256 + c2 * 2] = o;
    }
}

// ---------------- kernel 3: HMMA fused head ----------------
// smem (bytes): sxh f16[64][136] @0 (17408) | swh f16 nodeW[128][72] / outW[64][136] @17408 (18432)
// stn f16[64][72] @35840 (9216) | sagg f16[64][72] @45056 (9216)
// sattn f32[64] @54272 | sg f32[64] @54528 | smin f32[4][128] @54784 | smax @56832 ; total 58880
__global__ __launch_bounds__(256) void head_kernel(
    const float* __restrict__ x, const float* __restrict__ agg,
    const float* __restrict__ nodeW, const float* __restrict__ nodeB,
    const float* __restrict__ attnW, const float* __restrict__ attnB,
    const float* __restrict__ outW,  const float* __restrict__ outB,
    int h, float* __restrict__ upd,
    float* __restrict__ cmin, float* __restrict__ cmax,
    const float* __restrict__ pmin, const float* __restrict__ pmax) {
    extern __shared__ char smc[];
    __half* sxh  = (__half*)(smc);
    __half* swh  = (__half*)(smc + 17408);
    __half* stn  = (__half*)(smc + 35840);
    __half* sagg = (__half*)(smc + 45056);
    float* sattn = (float*)(smc + 54272);
    float* sg    = (float*)(smc + 54528);
    float* smin  = (float*)(smc + 54784);
    float* smax  = (float*)(smc + 56832);

    int t = threadIdx.x, lane = t & 31, w = t >> 5;
    int n0 = blockIdx.x * 64;
    bool dn = (pmin != nullptr);

    float xm = 0.f, xs = 1.f;          // norm params for fixed column q=t&127
    if (dn) {
        float mn = pmin[t & 127], mx = pmax[t & 127];
        xm = mn; xs = 1.f / (mx - mn + EPSV);
    }

    // ---- loads: x (norm+relu fused, f16), nodeW (f16), agg (f16), attnW ----
#pragma unroll
    for (int i = 0; i < 32; i++) {
        int L = i * 256 + t;
        int r = L >> 7, q = L & 127;
        float v = x[(size_t)(n0 + r) * ND + q];
        if (dn) v = fmaxf(0.f, (v - xm) * xs);
        sxh[r * 136 + q] = __float2half(v);
    }
    const float* nw = nodeW + (size_t)h * ND * HD;
#pragma unroll
    for (int i = 0; i < 32; i++) {
        int L = i * 256 + t;
        int k = L >> 6, n = L & 63;
        swh[k * 72 + n] = __float2half(nw[L]);
    }
#pragma unroll
    for (int i = 0; i < 16; i++) {
        int L = i * 256 + t;
        int r = L >> 6, c = L & 63;
        sagg[r * 72 + c] = __float2half(agg[(size_t)(n0 + r) * 256 + h * 64 + c]);
    }
    if (t < 64) sattn[t] = attnW[h * 64 + t];
    __syncthreads();

    int mw = w >> 1, nwp = w & 1;
    int g = lane >> 2, tig = lane & 3;

    // ---- GEMM1: tn(64x64) = x(64x128) @ nodeW(128x64), warp tile m16 x n32 ----
    {
        int m0 = mw * 16, nb = nwp * 32;
        float acc[4][4];
#pragma unroll
        for (int j = 0; j < 4; j++)
#pragma unroll
            for (int q = 0; q < 4; q++) acc[j][q] = 0.f;

        unsigned aBase = smem_u32(sxh) + (unsigned)(((m0 + (lane & 15)) * 136 + (lane >> 4) * 8) * 2);
        unsigned bBase = smem_u32(swh) + (unsigned)((((lane & 15)) * 72 + nb + (lane >> 4) * 8) * 2);
#pragma unroll
        for (int kk = 0; kk < 8; kk++) {
            int k0 = kk * 16;
            unsigned a0, a1, a2, a3, b0, b1, b2, b3, b4, b5, b6, b7;
            ldm_x4(aBase + k0 * 2, a0, a1, a2, a3);
            ldm_x4t(bBase + k0 * 72 * 2, b0, b1, b2, b3);
            ldm_x4t(bBase + k0 * 72 * 2 + 16 * 2, b4, b5, b6, b7);
            mma16816(acc[0][0], acc[0][1], acc[0][2], acc[0][3], a0, a1, a2, a3, b0, b1);
            mma16816(acc[1][0], acc[1][1], acc[1][2], acc[1][3], a0, a1, a2, a3, b2, b3);
            mma16816(acc[2][0], acc[2][1], acc[2][2], acc[2][3], a0, a1, a2, a3, b4, b5);
            mma16816(acc[3][0], acc[3][1], acc[3][2], acc[3][3], a0, a1, a2, a3, b6, b7);
        }
#pragma unroll
        for (int j = 0; j < 4; j++) {
            int cb = nb + j * 8 + tig * 2;
            float nb0 = __ldg(&nodeB[h * 64 + cb]);
            float nb1 = __ldg(&nodeB[h * 64 + cb + 1]);
            stn[(m0 + g) * 72 + cb]         = __float2half(acc[j][0] + nb0);
            stn[(m0 + g) * 72 + cb + 1]     = __float2half(acc[j][1] + nb1);
            stn[(m0 + g + 8) * 72 + cb]     = __float2half(acc[j][2] + nb0);
            stn[(m0 + g + 8) * 72 + cb + 1] = __float2half(acc[j][3] + nb1);
        }
    }
    __syncthreads();

    // ---- scores + gate (64 threads) overlapped with outW load (all threads) ----
    if (t < 64) {
        int r = t;
        float s = attnB[h];
#pragma unroll 8
        for (int c = 0; c < 64; c++)
            s += (__half2float(stn[r * 72 + c]) + __half2float(sagg[r * 72 + c])) * sattn[c];
        s = (s >= 0.f) ? s : 0.2f * s;
        sg[r] = 1.f / (1.f + expf(-s));
    }
    const float* ow = outW + (size_t)h * HD * OD;
#pragma unroll
    for (int i = 0; i < 32; i++) {
        int L = i * 256 + t;
        int k = L >> 7, n = L & 127;
        swh[k * 136 + n] = __float2half(ow[L]);
    }
    __syncthreads();

    // ---- u = g*agg + tn (in place in stn, f16) ----
#pragma unroll
    for (int i = 0; i < 16; i++) {
        int L = i * 256 + t;
        int r = L >> 6, c = L & 63;
        float uv = sg[r] * __half2float(sagg[r * 72 + c]) + __half2float(stn[r * 72 + c]);
        stn[r * 72 + c] = __float2half(uv);
    }
    __syncthreads();

    // ---- GEMM2: upd(64x128) = u(64x64) @ outW(64x128), warp tile m16 x n64 ----
    {
        int m0 = mw * 16, nb = nwp * 64;
        float acc[8][4];
#pragma unroll
        for (int j = 0; j < 8; j++)
#pragma unroll
            for (int q = 0; q < 4; q++) acc[j][q] = 0.f;

        unsigned aBase = smem_u32(stn) + (unsigned)(((m0 + (lane & 15)) * 72 + (lane >> 4) * 8) * 2);
        unsigned bBase = smem_u32(swh) + (unsigned)((((lane & 15)) * 136 + nb + (lane >> 4) * 8) * 2);
#pragma unroll
        for (int kk = 0; kk < 4; kk++) {
            int k0 = kk * 16;
            unsigned a0, a1, a2, a3;
            ldm_x4(aBase + k0 * 2, a0, a1, a2, a3);
#pragma unroll
            for (int s2 = 0; s2 < 4; s2++) {
                unsigned b0, b1, b2, b3;
                ldm_x4t(bBase + (k0 * 136 + s2 * 16) * 2, b0, b1, b2, b3);
                mma16816(acc[s2 * 2][0], acc[s2 * 2][1], acc[s2 * 2][2], acc[s2 * 2][3],
                         a0, a1, a2, a3, b0, b1);
                mma16816(acc[s2 * 2 + 1][0], acc[s2 * 2 + 1][1], acc[s2 * 2 + 1][2], acc[s2 * 2 + 1][3],
                         a0, a1, a2, a3, b2, b3);
            }
        }

        float mnA[8], mxA[8], mnB[8], mxB[8];
#pragma unroll
        for (int j = 0; j < 8; j++) {
            int cb = nb + j * 8 + tig * 2;
            float ob0 = __ldg(&outB[h * 128 + cb]);
            float ob1 = __ldg(&outB[h * 128 + cb + 1]);
            float o00 = acc[j][0] + ob0, o01 = acc[j][1] + ob1;
            float o10 = acc[j][2] + ob0, o11 = acc[j][3] + ob1;
            int r0g = n0 + m0 + g;
            *(float2*)&upd[(size_t)r0g * OD + cb]       = make_float2(o00, o01);
            *(float2*)&upd[(size_t)(r0g + 8) * OD + cb] = make_float2(o10, o11);
            mnA[j] = fminf(o00, o10); mxA[j] = fmaxf(o00, o10);
            mnB[j] = fminf(o01, o11); mxB[j] = fmaxf(o01, o11);
        }
#pragma unroll
        for (int d = 4; d <= 16; d <<= 1) {
#pragma unroll
            for (int j = 0; j < 8; j++) {
                mnA[j] = fminf(mnA[j], __shfl_xor_sync(0xffffffffu, mnA[j], d));
                mxA[j] = fmaxf(mxA[j], __shfl_xor_sync(0xffffffffu, mxA[j], d));
                mnB[j] = fminf(mnB[j], __shfl_xor_sync(0xffffffffu, mnB[j], d));
                mxB[j] = fmaxf(mxB[j], __shfl_xor_sync(0xffffffffu, mxB[j], d));
            }
        }
        if (lane < 4) {
#pragma unroll
            for (int j = 0; j < 8; j++) {
                int cb = nb + j * 8 + tig * 2;
                smin[mw * 128 + cb]     = mnA[j];
                smin[mw * 128 + cb + 1] = mnB[j];
                smax[mw * 128 + cb]     = mxA[j];
                smax[mw * 128 + cb + 1] = mxB[j];
            }
        }
    }
    __syncthreads();
    if (t < 128) {
        float m = smin[t], M = smax[t];
#pragma unroll
        for (int r = 1; r < 4; r++) {
            m = fminf(m, smin[r * 128 + t]);
            M = fmaxf(M, smax[r * 128 + t]);
        }
        atomicMinF(&cmin[t], m);
        atomicMaxF(&cmax[t], M);
    }
}

// ---------------- kernel 4: final norm ----------------
__global__ void norm_kernel(const float4* __restrict__ upd, const float* __restrict__ cmin,
                            const float* __restrict__ cmax, float4* __restrict__ dst) {
    __shared__ float sa[128], sb[128];
    int t = threadIdx.x;
    if (t < 128) {
        float mn = cmin[t], mx = cmax[t];
        sa[t] = 1.f / (mx - mn + EPSV);
        sb[t] = mn;
    }
    __syncthreads();
    int i = blockIdx.x * 256 + t;
    float4 v = upd[i];
    int c = (i & 31) * 4;
    float4 o;
    o.x = fmaxf(0.f, (v.x - sb[c + 0]) * sa[c + 0]);
    o.y = fmaxf(0.f, (v.y - sb[c + 1]) * sa[c + 1]);
    o.z = fmaxf(0.f, (v.z - sb[c + 2]) * sa[c + 2]);
    o.w = fmaxf(0.f, (v.w - sb[c + 3]) * sa[c + 3]);
    dst[i] = o;
}

// ---------------- launch ----------------
extern "C" void kernel_launch(void* const* d_in, const int* in_sizes, int n_in,
                              void* d_out, int out_size) {
    const float* nodeF = (const float*)d_in[0];
    const float* inc   = (const float*)d_in[1];
    const float* edgeF = (const float*)d_in[2];
    const float* nodeW = (const float*)d_in[3];
    const float* nodeB = (const float*)d_in[4];
    const float* edgeW = (const float*)d_in[5];
    const float* edgeB = (const float*)d_in[6];
    const float* attnW = (const float*)d_in[7];
    const float* attnB = (const float*)d_in[8];
    const float* outW  = (const float*)d_in[9];
    const float* outB  = (const float*)d_in[10];

    __half* te;  float *agg, *bufA, *bufB, *cmin, *cmax;
    cudaGetSymbolAddress((void**)&te,   g_te);
    cudaGetSymbolAddress((void**)&agg,  g_agg);
    cudaGetSymbolAddress((void**)&bufA, g_bufA);
    cudaGetSymbolAddress((void**)&bufB, g_bufB);
    cudaGetSymbolAddress((void**)&cmin, g_cmin);
    cudaGetSymbolAddress((void**)&cmax, g_cmax);

    const int hk_smem = 58880;
    cudaFuncSetAttribute(head_kernel, cudaFuncAttributeMaxDynamicSharedMemorySize, hk_smem);

    init_minmax_kernel<<<1, NH * OD>>>(cmin, cmax);
    te_kernel<<<N_EDGES / 32, 256>>>(edgeF, edgeW, edgeB, te);
    scan_kernel<<<N_NODES, 256>>>(inc, te, agg);

    float* bufs[2] = { bufA, bufB };
    const float* xin = nodeF;
    for (int h = 0; h < NH; h++) {
        float* dst = bufs[h & 1];
        const float* pmin = (h == 0) ? nullptr : cmin + (h - 1) * 128;
        const float* pmax = (h == 0) ? nullptr : cmax + (h - 1) * 128;
        head_kernel<<<N_NODES / 64, 256, hk_smem>>>(xin, agg, nodeW, nodeB, attnW, attnB,
                                                    outW, outB, h, dst,
                                                    cmin + h * 128, cmax + h * 128,
                                                    pmin, pmax);
        xin = dst;
    }
    norm_kernel<<<(N_NODES * OD / 4) / 256, 256>>>((const float4*)bufs[(NH - 1) & 1],
                                                   cmin + (NH - 1) * 128, cmax + (NH - 1) * 128,
                                                   (float4*)d_out);
}

// round 6
// speedup vs baseline: 2.3722x; 1.0989x over previous
#include <cuda_runtime.h>
#include <cuda_fp16.h>
#include <math.h>

#define N_NODES 32768
#define N_EDGES 8192
#define ND 128
#define ED 128
#define HD 64
#define OD 128
#define NH 4
#define EPSV 1e-8f

// ---------------- scratch ----------------
__device__ __half g_te[(size_t)N_EDGES * 256];
__device__ __half g_agg[(size_t)N_NODES * 256];   // fp16
__device__ float  g_bufA[(size_t)N_NODES * OD];
__device__ float  g_bufB[(size_t)N_NODES * OD];
__device__ float  g_cmin[NH * OD];
__device__ float  g_cmax[NH * OD];

// ---------------- helpers ----------------
__device__ __forceinline__ void atomicMinF(float* addr, float value) {
    if (value >= 0.f) atomicMin((int*)addr, __float_as_int(value));
    else              atomicMax((unsigned int*)addr, __float_as_uint(value));
}
__device__ __forceinline__ void atomicMaxF(float* addr, float value) {
    if (value >= 0.f) atomicMax((int*)addr, __float_as_int(value));
    else              atomicMin((unsigned int*)addr, __float_as_uint(value));
}
__device__ __forceinline__ unsigned smem_u32(const void* p) {
    return (unsigned)__cvta_generic_to_shared(p);
}
__device__ __forceinline__ void ldm_x4(unsigned addr, unsigned& r0, unsigned& r1,
                                       unsigned& r2, unsigned& r3) {
    asm volatile("ldmatrix.sync.aligned.m8n8.x4.shared.b16 {%0,%1,%2,%3}, [%4];"
                 : "=r"(r0), "=r"(r1), "=r"(r2), "=r"(r3) : "r"(addr));
}
__device__ __forceinline__ void ldm_x4t(unsigned addr, unsigned& r0, unsigned& r1,
                                        unsigned& r2, unsigned& r3) {
    asm volatile("ldmatrix.sync.aligned.m8n8.x4.trans.shared.b16 {%0,%1,%2,%3}, [%4];"
                 : "=r"(r0), "=r"(r1), "=r"(r2), "=r"(r3) : "r"(addr));
}
__device__ __forceinline__ void mma16816(float& c0, float& c1, float& c2, float& c3,
                                         unsigned a0, unsigned a1, unsigned a2, unsigned a3,
                                         unsigned b0, unsigned b1) {
    asm volatile("mma.sync.aligned.m16n8k16.row.col.f32.f16.f16.f32 "
                 "{%0,%1,%2,%3},{%4,%5,%6,%7},{%8,%9},{%0,%1,%2,%3};"
                 : "+f"(c0), "+f"(c1), "+f"(c2), "+f"(c3)
                 : "r"(a0), "r"(a1), "r"(a2), "r"(a3), "r"(b0), "r"(b1));
}
__device__ __forceinline__ unsigned pack2(float a, float b) {
    __half2 h = __floats2half2_rn(a, b);
    return *(unsigned*)&h;
}

// ---------------- kernel 0 ----------------
__global__ void init_minmax_kernel(float* cmin, float* cmax) {
    int t = threadIdx.x;
    cmin[t] =  __int_as_float(0x7f800000);
    cmax[t] = -__int_as_float(0x7f800000);
}

// ---------------- kernel 1: te (all heads, fp16 out) ----------------
// NOTE: sef stride must be 16B-aligned for float4 stores -> 132 floats (528B, 528%16==0).
__global__ void te_kernel(const float* __restrict__ ef, const float* __restrict__ edgeW,
                          const float* __restrict__ edgeB, __half* __restrict__ te) {
    __shared__ float sef[32][132];
    int t = threadIdx.x;
    int e0 = blockIdx.x * 32;
#pragma unroll
    for (int i = 0; i < 4; i++) {
        int L = i * 256 + t;
        int r = L >> 5, q4 = (L & 31) * 4;
        *(float4*)&sef[r][q4] = __ldg((const float4*)&ef[(size_t)(e0 + r) * ED + q4]);
    }
    __syncthreads();
    int h = t >> 6, c = t & 63;
    const float* W = edgeW + (size_t)h * ED * HD + c;
    float acc[32];
#pragma unroll
    for (int r = 0; r < 32; r++) acc[r] = 0.f;
    for (int k = 0; k < ED; k++) {
        float w = __ldg(W + k * HD);
#pragma unroll
        for (int r = 0; r < 32; r++) acc[r] += sef[r][k] * w;
    }
    float b = edgeB[h * HD + c];
#pragma unroll
    for (int r = 0; r < 32; r++)
        te[(size_t)(e0 + r) * 256 + t] = __float2half(acc[r] + b);
}

// ---------------- kernel 2: scan (mask compaction + half2 gather, fp16 agg out) ----------------
__global__ void scan_kernel(const float* __restrict__ inc, const __half* __restrict__ te,
                            __half* __restrict__ agg) {
    __shared__ int s_idx[512];
    __shared__ int s_wcnt[8];
    __shared__ float sxch[256];
    int t = threadIdx.x, w = t >> 5, l = t & 31;
    int n = blockIdx.x;

    const float4* row = (const float4*)(inc + (size_t)n * N_EDGES);
    unsigned mask = 0u;
#pragma unroll
    for (int i = 0; i < 8; i++) {
        float4 v = __ldcs(row + i * 256 + t);
        unsigned m = (v.x != 0.f ? 1u : 0u) | (v.y != 0.f ? 2u : 0u) |
                     (v.z != 0.f ? 4u : 0u) | (v.w != 0.f ? 8u : 0u);
        mask |= m << (i * 4);
    }
    int myc = __popc(mask);
    int pre = myc;
#pragma unroll
    for (int d = 1; d < 32; d <<= 1) {
        int o = __shfl_up_sync(0xffffffffu, pre, d);
        if (l >= d) pre += o;
    }
    int wtot = __shfl_sync(0xffffffffu, pre, 31);
    int myoff = pre - myc;
    if (l == 0) s_wcnt[w] = wtot;
    __syncthreads();

    int base = 0, cnt = 0;
#pragma unroll
    for (int w2 = 0; w2 < 8; w2++) {
        int c2 = s_wcnt[w2];
        if (w2 < w) base += c2;
        cnt += c2;
    }
    int pos = base + myoff;
    unsigned mm = mask;
    while (mm) {
        int b = __ffs(mm) - 1;
        mm &= mm - 1;
        s_idx[pos++] = ((b >> 2) * 256 + t) * 4 + (b & 3);
    }
    __syncthreads();

    float inv = 1.f / ((float)cnt + EPSV);

    int p = t >> 7, c2 = t & 127;
    const __half2* te2 = (const __half2*)te;
    float2 a0 = make_float2(0.f, 0.f), a1 = make_float2(0.f, 0.f);
    float2 a2 = make_float2(0.f, 0.f), a3 = make_float2(0.f, 0.f);
    int m = p;
    for (; m + 6 < cnt; m += 8) {
        float2 v0 = __half22float2(__ldg(&te2[(size_t)s_idx[m + 0] * 128 + c2]));
        float2 v1 = __half22float2(__ldg(&te2[(size_t)s_idx[m + 2] * 128 + c2]));
        float2 v2 = __half22float2(__ldg(&te2[(size_t)s_idx[m + 4] * 128 + c2]));
        float2 v3 = __half22float2(__ldg(&te2[(size_t)s_idx[m + 6] * 128 + c2]));
        a0.x += v0.x; a0.y += v0.y; a1.x += v1.x; a1.y += v1.y;
        a2.x += v2.x; a2.y += v2.y; a3.x += v3.x; a3.y += v3.y;
    }
    for (; m < cnt; m += 2) {
        float2 v = __half22float2(__ldg(&te2[(size_t)s_idx[m] * 128 + c2]));
        a0.x += v.x; a0.y += v.y;
    }
    float2 acc = make_float2((a0.x + a1.x) + (a2.x + a3.x),
                             (a0.y + a1.y) + (a2.y + a3.y));
    __syncthreads();
    if (p == 1) { sxch[c2 * 2] = acc.x; sxch[c2 * 2 + 1] = acc.y; }
    __syncthreads();
    if (p == 0) {
        __half2 o = __floats2half2_rn((acc.x + sxch[c2 * 2]) * inv,
                                      (acc.y + sxch[c2 * 2 + 1]) * inv);
        ((__half2*)agg)[(size_t)n * 128 + c2] = o;
    }
}

// ---------------- kernel 3: HMMA fused head (vectorized staging) ----------------
// smem: sxh f16[64][136] @0 (17408) | swh f16 nodeW[128][72]/outW[64][136] @17408 (18432)
// stn f16[64][72] @35840 (9216) | sagg f16[64][72] @45056 (9216)
// sattn f32[64] @54272 | sg f32[64] @54528 | smin f32[4][128] @54784 | smax @56832 ; total 58880
__global__ __launch_bounds__(256, 2) void head_kernel(
    const float* __restrict__ x, const __half* __restrict__ agg,
    const float* __restrict__ nodeW, const float* __restrict__ nodeB,
    const float* __restrict__ attnW, const float* __restrict__ attnB,
    const float* __restrict__ outW,  const float* __restrict__ outB,
    int h, float* __restrict__ upd,
    float* __restrict__ cmin, float* __restrict__ cmax,
    const float* __restrict__ pmin, const float* __restrict__ pmax) {
    extern __shared__ char smc[];
    __half* sxh  = (__half*)(smc);
    __half* swh  = (__half*)(smc + 17408);
    __half* stn  = (__half*)(smc + 35840);
    __half* sagg = (__half*)(smc + 45056);
    float* sattn = (float*)(smc + 54272);
    float* sg    = (float*)(smc + 54528);
    float* smin  = (float*)(smc + 54784);
    float* smax  = (float*)(smc + 56832);

    int t = threadIdx.x, lane = t & 31, w = t >> 5;
    int n0 = blockIdx.x * 64;
    bool dn = (pmin != nullptr);

    // ---- x tile: 8 x float4 per thread, fixed column group qg=lane*4 ----
    {
        int qg = lane * 4;
        float sa4[4], sb4[4];
        if (dn) {
#pragma unroll
            for (int j = 0; j < 4; j++) {
                float mn = __ldg(&pmin[qg + j]), mx = __ldg(&pmax[qg + j]);
                sb4[j] = mn; sa4[j] = 1.f / (mx - mn + EPSV);
            }
        }
#pragma unroll
        for (int i = 0; i < 8; i++) {
            int r = i * 8 + w;
            float4 v = __ldg((const float4*)&x[(size_t)(n0 + r) * ND + qg]);
            if (dn) {
                v.x = fmaxf(0.f, (v.x - sb4[0]) * sa4[0]);
                v.y = fmaxf(0.f, (v.y - sb4[1]) * sa4[1]);
                v.z = fmaxf(0.f, (v.z - sb4[2]) * sa4[2]);
                v.w = fmaxf(0.f, (v.w - sb4[3]) * sa4[3]);
            }
            *(uint2*)&sxh[r * 136 + qg] = make_uint2(pack2(v.x, v.y), pack2(v.z, v.w));
        }
    }
    // ---- nodeW: [128][64] -> swh stride 72 ----
    {
        const float* nw = nodeW + (size_t)h * ND * HD;
        int n4 = (t & 15) * 4;
#pragma unroll
        for (int i = 0; i < 8; i++) {
            int k = i * 16 + (t >> 4);
            float4 v = __ldg((const float4*)&nw[k * 64 + n4]);
            *(uint2*)&swh[k * 72 + n4] = make_uint2(pack2(v.x, v.y), pack2(v.z, v.w));
        }
    }
    // ---- agg tile (fp16 gmem): uint4 = 8 halves, 2 iters ----
    {
        int c8 = (t & 7) * 8;
#pragma unroll
        for (int i = 0; i < 2; i++) {
            int r = i * 32 + (t >> 3);
            uint4 v = __ldg((const uint4*)&agg[(size_t)(n0 + r) * 256 + h * 64 + c8]);
            *(uint4*)&sagg[r * 72 + c8] = v;
        }
    }
    if (t < 64) sattn[t] = attnW[h * 64 + t];
    __syncthreads();

    int mw = w >> 1, nwp = w & 1;
    int g = lane >> 2, tig = lane & 3;

    // ---- GEMM1: tn(64x64) = x(64x128) @ nodeW(128x64), warp m16 x n32 ----
    {
        int m0 = mw * 16, nb = nwp * 32;
        float acc[4][4];
#pragma unroll
        for (int j = 0; j < 4; j++)
#pragma unroll
            for (int q = 0; q < 4; q++) acc[j][q] = 0.f;

        unsigned aBase = smem_u32(sxh) + (unsigned)(((m0 + (lane & 15)) * 136 + (lane >> 4) * 8) * 2);
        unsigned bBase = smem_u32(swh) + (unsigned)((((lane & 15)) * 72 + nb + (lane >> 4) * 8) * 2);
#pragma unroll
        for (int kk = 0; kk < 8; kk++) {
            int k0 = kk * 16;
            unsigned a0, a1, a2, a3, b0, b1, b2, b3, b4, b5, b6, b7;
            ldm_x4(aBase + k0 * 2, a0, a1, a2, a3);
            ldm_x4t(bBase + k0 * 72 * 2, b0, b1, b2, b3);
            ldm_x4t(bBase + k0 * 72 * 2 + 16 * 2, b4, b5, b6, b7);
            mma16816(acc[0][0], acc[0][1], acc[0][2], acc[0][3], a0, a1, a2, a3, b0, b1);
            mma16816(acc[1][0], acc[1][1], acc[1][2], acc[1][3], a0, a1, a2, a3, b2, b3);
            mma16816(acc[2][0], acc[2][1], acc[2][2], acc[2][3], a0, a1, a2, a3, b4, b5);
            mma16816(acc[3][0], acc[3][1], acc[3][2], acc[3][3], a0, a1, a2, a3, b6, b7);
        }
#pragma unroll
        for (int j = 0; j < 4; j++) {
            int cb = nb + j * 8 + tig * 2;
            float nb0 = __ldg(&nodeB[h * 64 + cb]);
            float nb1 = __ldg(&nodeB[h * 64 + cb + 1]);
            stn[(m0 + g) * 72 + cb]         = __float2half(acc[j][0] + nb0);
            stn[(m0 + g) * 72 + cb + 1]     = __float2half(acc[j][1] + nb1);
            stn[(m0 + g + 8) * 72 + cb]     = __float2half(acc[j][2] + nb0);
            stn[(m0 + g + 8) * 72 + cb + 1] = __float2half(acc[j][3] + nb1);
        }
    }
    __syncthreads();

    // ---- scores + gate: all 8 warps, 8 rows each, 4 lanes per row ----
    {
        int r = w * 8 + (lane >> 2);
        int sub = lane & 3;
        float s = 0.f;
#pragma unroll
        for (int cc = 0; cc < 16; cc++) {
            int c = sub * 16 + cc;
            s += (__half2float(stn[r * 72 + c]) + __half2float(sagg[r * 72 + c])) * sattn[c];
        }
        s += __shfl_xor_sync(0xffffffffu, s, 1);
        s += __shfl_xor_sync(0xffffffffu, s, 2);
        if (sub == 0) {
            s += attnB[h];
            s = (s >= 0.f) ? s : 0.2f * s;
            sg[r] = 1.f / (1.f + expf(-s));
        }
    }
    // ---- outW load: [64][128] -> swh stride 136 ----
    {
        const float* ow = outW + (size_t)h * HD * OD;
        int n4 = (t & 31) * 4;
#pragma unroll
        for (int i = 0; i < 8; i++) {
            int k = i * 8 + (t >> 5);
            float4 v = __ldg((const float4*)&ow[k * 128 + n4]);
            *(uint2*)&swh[k * 136 + n4] = make_uint2(pack2(v.x, v.y), pack2(v.z, v.w));
        }
    }
    __syncthreads();

    // ---- u = g*agg + tn (half2, in place) ----
#pragma unroll
    for (int i = 0; i < 8; i++) {
        int L = i * 256 + t;
        int r = L >> 5, c2 = (L & 31) * 2;
        float gv = sg[r];
        float2 av = __half22float2(*(__half2*)&sagg[r * 72 + c2]);
        float2 tv = __half22float2(*(__half2*)&stn[r * 72 + c2]);
        *(__half2*)&stn[r * 72 + c2] = __floats2half2_rn(gv * av.x + tv.x, gv * av.y + tv.y);
    }
    __syncthreads();

    // ---- GEMM2: upd(64x128) = u(64x64) @ outW(64x128), warp m16 x n64 ----
    {
        int m0 = mw * 16, nb = nwp * 64;
        float acc[8][4];
#pragma unroll
        for (int j = 0; j < 8; j++)
#pragma unroll
            for (int q = 0; q < 4; q++) acc[j][q] = 0.f;

        unsigned aBase = smem_u32(stn) + (unsigned)(((m0 + (lane & 15)) * 72 + (lane >> 4) * 8) * 2);
        unsigned bBase = smem_u32(swh) + (unsigned)((((lane & 15)) * 136 + nb + (lane >> 4) * 8) * 2);
#pragma unroll
        for (int kk = 0; kk < 4; kk++) {
            int k0 = kk * 16;
            unsigned a0, a1, a2, a3;
            ldm_x4(aBase + k0 * 2, a0, a1, a2, a3);
#pragma unroll
            for (int s2 = 0; s2 < 4; s2++) {
                unsigned b0, b1, b2, b3;
                ldm_x4t(bBase + (k0 * 136 + s2 * 16) * 2, b0, b1, b2, b3);
                mma16816(acc[s2 * 2][0], acc[s2 * 2][1], acc[s2 * 2][2], acc[s2 * 2][3],
                         a0, a1, a2, a3, b0, b1);
                mma16816(acc[s2 * 2 + 1][0], acc[s2 * 2 + 1][1], acc[s2 * 2 + 1][2], acc[s2 * 2 + 1][3],
                         a0, a1, a2, a3, b2, b3);
            }
        }

        float mnA[8], mxA[8], mnB[8], mxB[8];
#pragma unroll
        for (int j = 0; j < 8; j++) {
            int cb = nb + j * 8 + tig * 2;
            float ob0 = __ldg(&outB[h * 128 + cb]);
            float ob1 = __ldg(&outB[h * 128 + cb + 1]);
            float o00 = acc[j][0] + ob0, o01 = acc[j][1] + ob1;
            float o10 = acc[j][2] + ob0, o11 = acc[j][3] + ob1;
            int r0g = n0 + m0 + g;
            *(float2*)&upd[(size_t)r0g * OD + cb]       = make_float2(o00, o01);
            *(float2*)&upd[(size_t)(r0g + 8) * OD + cb] = make_float2(o10, o11);
            mnA[j] = fminf(o00, o10); mxA[j] = fmaxf(o00, o10);
            mnB[j] = fminf(o01, o11); mxB[j] = fmaxf(o01, o11);
        }
#pragma unroll
        for (int d = 4; d <= 16; d <<= 1) {
#pragma unroll
            for (int j = 0; j < 8; j++) {
                mnA[j] = fminf(mnA[j], __shfl_xor_sync(0xffffffffu, mnA[j], d));
                mxA[j] = fmaxf(mxA[j], __shfl_xor_sync(0xffffffffu, mxA[j], d));
                mnB[j] = fminf(mnB[j], __shfl_xor_sync(0xffffffffu, mnB[j], d));
                mxB[j] = fmaxf(mxB[j], __shfl_xor_sync(0xffffffffu, mxB[j], d));
            }
        }
        if (lane < 4) {
#pragma unroll
            for (int j = 0; j < 8; j++) {
                int cb = nb + j * 8 + tig * 2;
                smin[mw * 128 + cb]     = mnA[j];
                smin[mw * 128 + cb + 1] = mnB[j];
                smax[mw * 128 + cb]     = mxA[j];
                smax[mw * 128 + cb + 1] = mxB[j];
            }
        }
    }
    __syncthreads();
    if (t < 128) {
        float m = smin[t], M = smax[t];
#pragma unroll
        for (int r = 1; r < 4; r++) {
            m = fminf(m, smin[r * 128 + t]);
            M = fmaxf(M, smax[r * 128 + t]);
        }
        atomicMinF(&cmin[t], m);
        atomicMaxF(&cmax[t], M);
    }
}

// ---------------- kernel 4: final norm ----------------
__global__ void norm_kernel(const float4* __restrict__ upd, const float* __restrict__ cmin,
                            const float* __restrict__ cmax, float4* __restrict__ dst) {
    __shared__ float sa[128], sb[128];
    int t = threadIdx.x;
    if (t < 128) {
        float mn = cmin[t], mx = cmax[t];
        sa[t] = 1.f / (mx - mn + EPSV);
        sb[t] = mn;
    }
    __syncthreads();
    int i = blockIdx.x * 256 + t;
    float4 v = upd[i];
    int c = (i & 31) * 4;
    float4 o;
    o.x = fmaxf(0.f, (v.x - sb[c + 0]) * sa[c + 0]);
    o.y = fmaxf(0.f, (v.y - sb[c + 1]) * sa[c + 1]);
    o.z = fmaxf(0.f, (v.z - sb[c + 2]) * sa[c + 2]);
    o.w = fmaxf(0.f, (v.w - sb[c + 3]) * sa[c + 3]);
    dst[i] = o;
}

// ---------------- launch ----------------
extern "C" void kernel_launch(void* const* d_in, const int* in_sizes, int n_in,
                              void* d_out, int out_size) {
    const float* nodeF = (const float*)d_in[0];
    const float* inc   = (const float*)d_in[1];
    const float* edgeF = (const float*)d_in[2];
    const float* nodeW = (const float*)d_in[3];
    const float* nodeB = (const float*)d_in[4];
    const float* edgeW = (const float*)d_in[5];
    const float* edgeB = (const float*)d_in[6];
    const float* attnW = (const float*)d_in[7];
    const float* attnB = (const float*)d_in[8];
    const float* outW  = (const float*)d_in[9];
    const float* outB  = (const float*)d_in[10];

    __half *te, *agg;  float *bufA, *bufB, *cmin, *cmax;
    cudaGetSymbolAddress((void**)&te,   g_te);
    cudaGetSymbolAddress((void**)&agg,  g_agg);
    cudaGetSymbolAddress((void**)&bufA, g_bufA);
    cudaGetSymbolAddress((void**)&bufB, g_bufB);
    cudaGetSymbolAddress((void**)&cmin, g_cmin);
    cudaGetSymbolAddress((void**)&cmax, g_cmax);

    const int hk_smem = 58880;
    cudaFuncSetAttribute(head_kernel, cudaFuncAttributeMaxDynamicSharedMemorySize, hk_smem);

    init_minmax_kernel<<<1, NH * OD>>>(cmin, cmax);
    te_kernel<<<N_EDGES / 32, 256>>>(edgeF, edgeW, edgeB, te);
    scan_kernel<<<N_NODES, 256>>>(inc, te, agg);

    float* bufs[2] = { bufA, bufB };
    const float* xin = nodeF;
    for (int h = 0; h < NH; h++) {
        float* dst = bufs[h & 1];
        const float* pmin = (h == 0) ? nullptr : cmin + (h - 1) * 128;
        const float* pmax = (h == 0) ? nullptr : cmax + (h - 1) * 128;
        head_kernel<<<N_NODES / 64, 256, hk_smem>>>(xin, agg, nodeW, nodeB, attnW, attnB,
                                                    outW, outB, h, dst,
                                                    cmin + h * 128, cmax + h * 128,
                                                    pmin, pmax);
        xin = dst;
    }
    norm_kernel<<<(N_NODES * OD / 4) / 256, 256>>>((const float4*)bufs[(NH - 1) & 1],
                                                   cmin + (NH - 1) * 128, cmax + (NH - 1) * 128,
                                                   (float4*)d_out);
}

// round 7
// speedup vs baseline: 2.4206x; 1.0204x over previous
#include <cuda_runtime.h>
#include <cuda_fp16.h>
#include <math.h>

#define N_NODES 32768
#define N_EDGES 8192
#define ND 128
#define ED 128
#define HD 64
#define OD 128
#define NH 4
#define EPSV 1e-8f

// ---------------- scratch ----------------
__device__ __half g_te[(size_t)N_EDGES * 256];
__device__ __half g_agg[(size_t)N_NODES * 256];
__device__ __half g_nodeWh[NH * ND * HD];
__device__ __half g_outWh[NH * HD * OD];
__device__ float  g_bufA[(size_t)N_NODES * OD];
__device__ float  g_bufB[(size_t)N_NODES * OD];
__device__ float  g_cmin[NH * OD];
__device__ float  g_cmax[NH * OD];

// ---------------- helpers ----------------
__device__ __forceinline__ void atomicMinF(float* addr, float value) {
    if (value >= 0.f) atomicMin((int*)addr, __float_as_int(value));
    else              atomicMax((unsigned int*)addr, __float_as_uint(value));
}
__device__ __forceinline__ void atomicMaxF(float* addr, float value) {
    if (value >= 0.f) atomicMax((int*)addr, __float_as_int(value));
    else              atomicMin((unsigned int*)addr, __float_as_uint(value));
}
__device__ __forceinline__ unsigned smem_u32(const void* p) {
    return (unsigned)__cvta_generic_to_shared(p);
}
__device__ __forceinline__ void ldm_x4(unsigned addr, unsigned& r0, unsigned& r1,
                                       unsigned& r2, unsigned& r3) {
    asm volatile("ldmatrix.sync.aligned.m8n8.x4.shared.b16 {%0,%1,%2,%3}, [%4];"
                 : "=r"(r0), "=r"(r1), "=r"(r2), "=r"(r3) : "r"(addr));
}
__device__ __forceinline__ void ldm_x4t(unsigned addr, unsigned& r0, unsigned& r1,
                                        unsigned& r2, unsigned& r3) {
    asm volatile("ldmatrix.sync.aligned.m8n8.x4.trans.shared.b16 {%0,%1,%2,%3}, [%4];"
                 : "=r"(r0), "=r"(r1), "=r"(r2), "=r"(r3) : "r"(addr));
}
__device__ __forceinline__ void mma16816(float& c0, float& c1, float& c2, float& c3,
                                         unsigned a0, unsigned a1, unsigned a2, unsigned a3,
                                         unsigned b0, unsigned b1) {
    asm volatile("mma.sync.aligned.m16n8k16.row.col.f32.f16.f16.f32 "
                 "{%0,%1,%2,%3},{%4,%5,%6,%7},{%8,%9},{%0,%1,%2,%3};"
                 : "+f"(c0), "+f"(c1), "+f"(c2), "+f"(c3)
                 : "r"(a0), "r"(a1), "r"(a2), "r"(a3), "r"(b0), "r"(b1));
}
__device__ __forceinline__ unsigned pack2(float a, float b) {
    __half2 h = __floats2half2_rn(a, b);
    return *(unsigned*)&h;
}

// ---------------- kernel 0: init + weight fp16 conversion ----------------
__global__ void init_minmax_kernel(float* cmin, float* cmax) {
    int t = threadIdx.x;
    cmin[t] =  __int_as_float(0x7f800000);
    cmax[t] = -__int_as_float(0x7f800000);
}
__global__ void cvt_w_kernel(const float* __restrict__ nodeW, const float* __restrict__ outW,
                             __half* __restrict__ nodeWh, __half* __restrict__ outWh) {
    int i = blockIdx.x * 256 + threadIdx.x;     // 32768 each
    nodeWh[i] = __float2half(nodeW[i]);
    outWh[i]  = __float2half(outW[i]);
}

// ---------------- kernel 1: te (all heads, fp16 out) ----------------
__global__ void te_kernel(const float* __restrict__ ef, const float* __restrict__ edgeW,
                          const float* __restrict__ edgeB, __half* __restrict__ te) {
    __shared__ float sef[32][132];               // stride 528B, 16B-aligned
    int t = threadIdx.x;
    int e0 = blockIdx.x * 32;
#pragma unroll
    for (int i = 0; i < 4; i++) {
        int L = i * 256 + t;
        int r = L >> 5, q4 = (L & 31) * 4;
        *(float4*)&sef[r][q4] = __ldg((const float4*)&ef[(size_t)(e0 + r) * ED + q4]);
    }
    __syncthreads();
    int h = t >> 6, c = t & 63;
    const float* W = edgeW + (size_t)h * ED * HD + c;
    float acc[32];
#pragma unroll
    for (int r = 0; r < 32; r++) acc[r] = 0.f;
    for (int k = 0; k < ED; k++) {
        float w = __ldg(W + k * HD);
#pragma unroll
        for (int r = 0; r < 32; r++) acc[r] += sef[r][k] * w;
    }
    float b = edgeB[h * HD + c];
#pragma unroll
    for (int r = 0; r < 32; r++)
        te[(size_t)(e0 + r) * 256 + t] = __float2half(acc[r] + b);
}

// ---------------- kernel 2: scan (mask compaction + half2 gather, fp16 agg out) ----------------
__global__ void scan_kernel(const float* __restrict__ inc, const __half* __restrict__ te,
                            __half* __restrict__ agg) {
    __shared__ int s_idx[512];
    __shared__ int s_wcnt[8];
    __shared__ float sxch[256];
    int t = threadIdx.x, w = t >> 5, l = t & 31;
    int n = blockIdx.x;

    const float4* row = (const float4*)(inc + (size_t)n * N_EDGES);
    unsigned mask = 0u;
#pragma unroll
    for (int i = 0; i < 8; i++) {
        float4 v = __ldcs(row + i * 256 + t);
        unsigned m = (v.x != 0.f ? 1u : 0u) | (v.y != 0.f ? 2u : 0u) |
                     (v.z != 0.f ? 4u : 0u) | (v.w != 0.f ? 8u : 0u);
        mask |= m << (i * 4);
    }
    int myc = __popc(mask);
    int pre = myc;
#pragma unroll
    for (int d = 1; d < 32; d <<= 1) {
        int o = __shfl_up_sync(0xffffffffu, pre, d);
        if (l >= d) pre += o;
    }
    int wtot = __shfl_sync(0xffffffffu, pre, 31);
    int myoff = pre - myc;
    if (l == 0) s_wcnt[w] = wtot;
    __syncthreads();

    int base = 0, cnt = 0;
#pragma unroll
    for (int w2 = 0; w2 < 8; w2++) {
        int c2 = s_wcnt[w2];
        if (w2 < w) base += c2;
        cnt += c2;
    }
    int pos = base + myoff;
    unsigned mm = mask;
    while (mm) {
        int b = __ffs(mm) - 1;
        mm &= mm - 1;
        s_idx[pos++] = ((b >> 2) * 256 + t) * 4 + (b & 3);
    }
    __syncthreads();

    float inv = 1.f / ((float)cnt + EPSV);

    int p = t >> 7, c2 = t & 127;
    const __half2* te2 = (const __half2*)te;
    float2 a0 = make_float2(0.f, 0.f), a1 = make_float2(0.f, 0.f);
    float2 a2 = make_float2(0.f, 0.f), a3 = make_float2(0.f, 0.f);
    int m = p;
    for (; m + 6 < cnt; m += 8) {
        float2 v0 = __half22float2(__ldg(&te2[(size_t)s_idx[m + 0] * 128 + c2]));
        float2 v1 = __half22float2(__ldg(&te2[(size_t)s_idx[m + 2] * 128 + c2]));
        float2 v2 = __half22float2(__ldg(&te2[(size_t)s_idx[m + 4] * 128 + c2]));
        float2 v3 = __half22float2(__ldg(&te2[(size_t)s_idx[m + 6] * 128 + c2]));
        a0.x += v0.x; a0.y += v0.y; a1.x += v1.x; a1.y += v1.y;
        a2.x += v2.x; a2.y += v2.y; a3.x += v3.x; a3.y += v3.y;
    }
    for (; m < cnt; m += 2) {
        float2 v = __half22float2(__ldg(&te2[(size_t)s_idx[m] * 128 + c2]));
        a0.x += v.x; a0.y += v.y;
    }
    float2 acc = make_float2((a0.x + a1.x) + (a2.x + a3.x),
                             (a0.y + a1.y) + (a2.y + a3.y));
    __syncthreads();
    if (p == 1) { sxch[c2 * 2] = acc.x; sxch[c2 * 2 + 1] = acc.y; }
    __syncthreads();
    if (p == 0) {
        __half2 o = __floats2half2_rn((acc.x + sxch[c2 * 2]) * inv,
                                      (acc.y + sxch[c2 * 2 + 1]) * inv);
        ((__half2*)agg)[(size_t)n * 128 + c2] = o;
    }
}

// ---------------- kernel 3: HMMA fused head, 128 rows/block (single wave) ----------------
// smem bytes: sxh f16[128][136] @0 (34816) | swh @34816: nodeW f16[128][72] (18432) / outW f16[64][136] (17408)
// stn f16[128][72] @53248 (18432) | sagg f16[128][72] @71680 (18432)
// sattn f32[64] @90112 | sg f32[128] @90368 | smin f32[4][128] @90880 | smax @92928 ; total 94976
__global__ __launch_bounds__(256, 2) void head_kernel(
    const float* __restrict__ x, const __half* __restrict__ agg,
    const __half* __restrict__ nodeWh, const float* __restrict__ nodeB,
    const float* __restrict__ attnW, const float* __restrict__ attnB,
    const __half* __restrict__ outWh, const float* __restrict__ outB,
    int h, float* __restrict__ upd,
    float* __restrict__ cmin, float* __restrict__ cmax,
    const float* __restrict__ pmin, const float* __restrict__ pmax) {
    extern __shared__ char smc[];
    __half* sxh  = (__half*)(smc);
    __half* swh  = (__half*)(smc + 34816);
    __half* stn  = (__half*)(smc + 53248);
    __half* sagg = (__half*)(smc + 71680);
    float* sattn = (float*)(smc + 90112);
    float* sg    = (float*)(smc + 90368);
    float* smin  = (float*)(smc + 90880);
    float* smax  = (float*)(smc + 92928);

    int t = threadIdx.x, lane = t & 31, w = t >> 5;
    int n0 = blockIdx.x * 128;
    bool dn = (pmin != nullptr);

    // ---- x tile: 16 x float4 per thread, fixed col group qg = lane*4 ----
    {
        int qg = lane * 4;
        float sa4[4], sb4[4];
        if (dn) {
#pragma unroll
            for (int j = 0; j < 4; j++) {
                float mn = __ldg(&pmin[qg + j]), mx = __ldg(&pmax[qg + j]);
                sb4[j] = mn; sa4[j] = 1.f / (mx - mn + EPSV);
            }
        }
#pragma unroll
        for (int i = 0; i < 16; i++) {
            int r = i * 8 + w;
            float4 v = __ldg((const float4*)&x[(size_t)(n0 + r) * ND + qg]);
            if (dn) {
                v.x = fmaxf(0.f, (v.x - sb4[0]) * sa4[0]);
                v.y = fmaxf(0.f, (v.y - sb4[1]) * sa4[1]);
                v.z = fmaxf(0.f, (v.z - sb4[2]) * sa4[2]);
                v.w = fmaxf(0.f, (v.w - sb4[3]) * sa4[3]);
            }
            *(uint2*)&sxh[r * 136 + qg] = make_uint2(pack2(v.x, v.y), pack2(v.z, v.w));
        }
    }
    // ---- nodeW fp16: 4 x uint4 per thread -> swh stride 72 ----
    {
        const __half* nw = nodeWh + h * (ND * HD);
#pragma unroll
        for (int i = 0; i < 4; i++) {
            int idx = i * 256 + t;
            int k = idx >> 3, n8 = (idx & 7) * 8;
            *(uint4*)&swh[k * 72 + n8] = __ldg((const uint4*)&nw[idx * 8]);
        }
    }
    // ---- agg tile (fp16): 4 x uint4 per thread ----
    {
        int c8 = (t & 7) * 8;
#pragma unroll
        for (int i = 0; i < 4; i++) {
            int r = i * 32 + (t >> 3);
            *(uint4*)&sagg[r * 72 + c8] =
                __ldg((const uint4*)&agg[(size_t)(n0 + r) * 256 + h * 64 + c8]);
        }
    }
    if (t < 64) sattn[t] = attnW[h * 64 + t];
    __syncthreads();

    int mw = w >> 1, nwp = w & 1;
    int g = lane >> 2, tig = lane & 3;

    // ---- GEMM1: tn(128x64) = x(128x128) @ nodeW(128x64); warp m32(x2 m16) x n32 ----
    {
        int m0 = mw * 32, nb = nwp * 32;
#pragma unroll
        for (int msub = 0; msub < 32; msub += 16) {
            float acc[4][4];
#pragma unroll
            for (int j = 0; j < 4; j++)
#pragma unroll
                for (int q = 0; q < 4; q++) acc[j][q] = 0.f;

            unsigned aBase = smem_u32(sxh) +
                (unsigned)(((m0 + msub + (lane & 15)) * 136 + (lane >> 4) * 8) * 2);
            unsigned bBase = smem_u32(swh) +
                (unsigned)((((lane & 15)) * 72 + nb + (lane >> 4) * 8) * 2);
#pragma unroll
            for (int kk = 0; kk < 8; kk++) {
                int k0 = kk * 16;
                unsigned a0, a1, a2, a3, b0, b1, b2, b3, b4, b5, b6, b7;
                ldm_x4(aBase + k0 * 2, a0, a1, a2, a3);
                ldm_x4t(bBase + k0 * 72 * 2, b0, b1, b2, b3);
                ldm_x4t(bBase + k0 * 72 * 2 + 32, b4, b5, b6, b7);
                mma16816(acc[0][0], acc[0][1], acc[0][2], acc[0][3], a0, a1, a2, a3, b0, b1);
                mma16816(acc[1][0], acc[1][1], acc[1][2], acc[1][3], a0, a1, a2, a3, b2, b3);
                mma16816(acc[2][0], acc[2][1], acc[2][2], acc[2][3], a0, a1, a2, a3, b4, b5);
                mma16816(acc[3][0], acc[3][1], acc[3][2], acc[3][3], a0, a1, a2, a3, b6, b7);
            }
#pragma unroll
            for (int j = 0; j < 4; j++) {
                int cb = nb + j * 8 + tig * 2;
                float nb0 = __ldg(&nodeB[h * 64 + cb]);
                float nb1 = __ldg(&nodeB[h * 64 + cb + 1]);
                int rr = m0 + msub + g;
                stn[rr * 72 + cb]           = __float2half(acc[j][0] + nb0);
                stn[rr * 72 + cb + 1]       = __float2half(acc[j][1] + nb1);
                stn[(rr + 8) * 72 + cb]     = __float2half(acc[j][2] + nb0);
                stn[(rr + 8) * 72 + cb + 1] = __float2half(acc[j][3] + nb1);
            }
        }
    }
    __syncthreads();

    // ---- scores + gate: 16 rows/warp, 2 lanes/row ----
    {
        int r = w * 16 + (lane >> 1);
        int sub = lane & 1;
        float s = 0.f;
#pragma unroll
        for (int cc = 0; cc < 32; cc++) {
            int c = sub * 32 + cc;
            s += (__half2float(stn[r * 72 + c]) + __half2float(sagg[r * 72 + c])) * sattn[c];
        }
        s += __shfl_xor_sync(0xffffffffu, s, 1);
        if (sub == 0) {
            s += attnB[h];
            s = (s >= 0.f) ? s : 0.2f * s;
            sg[r] = 1.f / (1.f + expf(-s));
        }
    }
    // ---- outW fp16 load: 4 x uint4 per thread -> swh stride 136 ----
    {
        const __half* ow = outWh + h * (HD * OD);
#pragma unroll
        for (int i = 0; i < 4; i++) {
            int idx = i * 256 + t;
            int k = idx >> 4, n8 = (idx & 15) * 8;
            *(uint4*)&swh[k * 136 + n8] = __ldg((const uint4*)&ow[idx * 8]);
        }
    }
    __syncthreads();

    // ---- u = g*agg + tn (half2, in place) ----
#pragma unroll
    for (int i = 0; i < 16; i++) {
        int L = i * 256 + t;
        int r = L >> 5, c2 = (L & 31) * 2;
        float gv = sg[r];
        float2 av = __half22float2(*(__half2*)&sagg[r * 72 + c2]);
        float2 tv = __half22float2(*(__half2*)&stn[r * 72 + c2]);
        *(__half2*)&stn[r * 72 + c2] = __floats2half2_rn(gv * av.x + tv.x, gv * av.y + tv.y);
    }
    __syncthreads();

    // ---- GEMM2: upd(128x128) = u(128x64) @ outW(64x128); warp m32(x2 m16) x n64 ----
    {
        int m0 = mw * 32, nb = nwp * 64;
        float mnA[8], mxA[8], mnB[8], mxB[8];
#pragma unroll
        for (int j = 0; j < 8; j++) {
            mnA[j] = 3.4e38f; mxA[j] = -3.4e38f;
            mnB[j] = 3.4e38f; mxB[j] = -3.4e38f;
        }
#pragma unroll
        for (int msub = 0; msub < 32; msub += 16) {
            float acc[8][4];
#pragma unroll
            for (int j = 0; j < 8; j++)
#pragma unroll
                for (int q = 0; q < 4; q++) acc[j][q] = 0.f;

            unsigned aBase = smem_u32(stn) +
                (unsigned)(((m0 + msub + (lane & 15)) * 72 + (lane >> 4) * 8) * 2);
            unsigned bBase = smem_u32(swh) +
                (unsigned)((((lane & 15)) * 136 + nb + (lane >> 4) * 8) * 2);
#pragma unroll
            for (int kk = 0; kk < 4; kk++) {
                int k0 = kk * 16;
                unsigned a0, a1, a2, a3;
                ldm_x4(aBase + k0 * 2, a0, a1, a2, a3);
#pragma unroll
                for (int s2 = 0; s2 < 4; s2++) {
                    unsigned b0, b1, b2, b3;
                    ldm_x4t(bBase + (k0 * 136 + s2 * 16) * 2, b0, b1, b2, b3);
                    mma16816(acc[s2 * 2][0], acc[s2 * 2][1], acc[s2 * 2][2], acc[s2 * 2][3],
                             a0, a1, a2, a3, b0, b1);
                    mma16816(acc[s2 * 2 + 1][0], acc[s2 * 2 + 1][1], acc[s2 * 2 + 1][2],
                             acc[s2 * 2 + 1][3], a0, a1, a2, a3, b2, b3);
                }
            }
#pragma unroll
            for (int j = 0; j < 8; j++) {
                int cb = nb + j * 8 + tig * 2;
                float ob0 = __ldg(&outB[h * 128 + cb]);
                float ob1 = __ldg(&outB[h * 128 + cb + 1]);
                float o00 = acc[j][0] + ob0, o01 = acc[j][1] + ob1;
                float o10 = acc[j][2] + ob0, o11 = acc[j][3] + ob1;
                int r0g = n0 + m0 + msub + g;
                *(float2*)&upd[(size_t)r0g * OD + cb]       = make_float2(o00, o01);
                *(float2*)&upd[(size_t)(r0g + 8) * OD + cb] = make_float2(o10, o11);
                mnA[j] = fminf(mnA[j], fminf(o00, o10)); mxA[j] = fmaxf(mxA[j], fmaxf(o00, o10));
                mnB[j] = fminf(mnB[j], fminf(o01, o11)); mxB[j] = fmaxf(mxB[j], fmaxf(o01, o11));
            }
        }
#pragma unroll
        for (int d = 4; d <= 16; d <<= 1) {
#pragma unroll
            for (int j = 0; j < 8; j++) {
                mnA[j] = fminf(mnA[j], __shfl_xor_sync(0xffffffffu, mnA[j], d));
                mxA[j] = fmaxf(mxA[j], __shfl_xor_sync(0xffffffffu, mxA[j], d));
                mnB[j] = fminf(mnB[j], __shfl_xor_sync(0xffffffffu, mnB[j], d));
                mxB[j] = fmaxf(mxB[j], __shfl_xor_sync(0xffffffffu, mxB[j], d));
            }
        }
        if (lane < 4) {
#pragma unroll
            for (int j = 0; j < 8; j++) {
                int cb = nb + j * 8 + tig * 2;
                smin[mw * 128 + cb]     = mnA[j];
                smin[mw * 128 + cb + 1] = mnB[j];
                smax[mw * 128 + cb]     = mxA[j];
                smax[mw * 128 + cb + 1] = mxB[j];
            }
        }
    }
    __syncthreads();
    if (t < 128) {
        float m = smin[t], M = smax[t];
#pragma unroll
        for (int r = 1; r < 4; r++) {
            m = fminf(m, smin[r * 128 + t]);
            M = fmaxf(M, smax[r * 128 + t]);
        }
        atomicMinF(&cmin[t], m);
        atomicMaxF(&cmax[t], M);
    }
}

// ---------------- kernel 4: final norm ----------------
__global__ void norm_kernel(const float4* __restrict__ upd, const float* __restrict__ cmin,
                            const float* __restrict__ cmax, float4* __restrict__ dst) {
    __shared__ float sa[128], sb[128];
    int t = threadIdx.x;
    if (t < 128) {
        float mn = cmin[t], mx = cmax[t];
        sa[t] = 1.f / (mx - mn + EPSV);
        sb[t] = mn;
    }
    __syncthreads();
    int i = blockIdx.x * 256 + t;
    float4 v = upd[i];
    int c = (i & 31) * 4;
    float4 o;
    o.x = fmaxf(0.f, (v.x - sb[c + 0]) * sa[c + 0]);
    o.y = fmaxf(0.f, (v.y - sb[c + 1]) * sa[c + 1]);
    o.z = fmaxf(0.f, (v.z - sb[c + 2]) * sa[c + 2]);
    o.w = fmaxf(0.f, (v.w - sb[c + 3]) * sa[c + 3]);
    dst[i] = o;
}

// ---------------- launch ----------------
extern "C" void kernel_launch(void* const* d_in, const int* in_sizes, int n_in,
                              void* d_out, int out_size) {
    const float* nodeF = (const float*)d_in[0];
    const float* inc   = (const float*)d_in[1];
    const float* edgeF = (const float*)d_in[2];
    const float* nodeW = (const float*)d_in[3];
    const float* nodeB = (const float*)d_in[4];
    const float* edgeW = (const float*)d_in[5];
    const float* edgeB = (const float*)d_in[6];
    const float* attnW = (const float*)d_in[7];
    const float* attnB = (const float*)d_in[8];
    const float* outW  = (const float*)d_in[9];
    const float* outB  = (const float*)d_in[10];

    __half *te, *agg, *nodeWh, *outWh;  float *bufA, *bufB, *cmin, *cmax;
    cudaGetSymbolAddress((void**)&te,     g_te);
    cudaGetSymbolAddress((void**)&agg,    g_agg);
    cudaGetSymbolAddress((void**)&nodeWh, g_nodeWh);
    cudaGetSymbolAddress((void**)&outWh,  g_outWh);
    cudaGetSymbolAddress((void**)&bufA,   g_bufA);
    cudaGetSymbolAddress((void**)&bufB,   g_bufB);
    cudaGetSymbolAddress((void**)&cmin,   g_cmin);
    cudaGetSymbolAddress((void**)&cmax,   g_cmax);

    const int hk_smem = 94976;
    cudaFuncSetAttribute(head_kernel, cudaFuncAttributeMaxDynamicSharedMemorySize, hk_smem);

    init_minmax_kernel<<<1, NH * OD>>>(cmin, cmax);
    cvt_w_kernel<<<NH * ND * HD / 256, 256>>>(nodeW, outW, nodeWh, outWh);
    te_kernel<<<N_EDGES / 32, 256>>>(edgeF, edgeW, edgeB, te);
    scan_kernel<<<N_NODES, 256>>>(inc, te, agg);

    float* bufs[2] = { bufA, bufB };
    const float* xin = nodeF;
    for (int h = 0; h < NH; h++) {
        float* dst = bufs[h & 1];
        const float* pmin = (h == 0) ? nullptr : cmin + (h - 1) * 128;
        const float* pmax = (h == 0) ? nullptr : cmax + (h - 1) * 128;
        head_kernel<<<N_NODES / 128, 256, hk_smem>>>(xin, agg, nodeWh, nodeB, attnW, attnB,
                                                     outWh, outB, h, dst,
                                                     cmin + h * 128, cmax + h * 128,
                                                     pmin, pmax);
        xin = dst;
    }
    norm_kernel<<<(N_NODES * OD / 4) / 256, 256>>>((const float4*)bufs[(NH - 1) & 1],
                                                   cmin + (NH - 1) * 128, cmax + (NH - 1) * 128,
                                                   (float4*)d_out);
}